// round 1
// baseline (speedup 1.0000x reference)
#include <cuda_runtime.h>
#include <math.h>

#define Bn 8
#define Hn 8
#define Sn 1024
#define DMn 512
#define DKn 64
#define MROWS (Bn * Sn)   // 8192

// ---------------- scratch (device globals; no allocation allowed) ----------------
__device__ float g_Qr[Bn * Hn * Sn * DKn];
__device__ float g_Kr[Bn * Hn * Sn * DKn];
__device__ float g_Vr[Bn * Hn * Sn * DKn];
__device__ float g_Qf[Bn * Hn * Sn * DKn];
__device__ float g_Kf[Bn * Hn * Sn * DKn];
__device__ float g_Vf[Bn * Hn * Sn * DKn];
__device__ float g_Sr[(size_t)Bn * Hn * Sn * Sn];   // 256 MB; reused in-place for merged P
__device__ float g_Sf[(size_t)Bn * Hn * Sn * Sn];   // 256 MB
__device__ float g_Cr[MROWS * DMn];
__device__ float g_Cf[MROWS * DMn];

// ---------------- fast exp (avoid MUFU throughput wall) ----------------
__device__ __forceinline__ float fexp(float x) {
    // x <= 0 here (max-subtracted). exp(x) = 2^(x*log2e)
    float t  = x * 1.4426950408889634f;
    float fi = rintf(t);
    float f  = t - fi;                     // f in [-0.5, 0.5]
    float p  = 1.3333558146428443e-3f;     // Taylor for 2^f, rel err ~2e-6
    p = fmaf(p, f, 9.6181291076284770e-3f);
    p = fmaf(p, f, 5.5504108664821580e-2f);
    p = fmaf(p, f, 2.4022650695910072e-1f);
    p = fmaf(p, f, 6.9314718055994531e-1f);
    p = fmaf(p, f, 1.0f);
    int e = (int)fi;
    return __int_as_float(__float_as_int(p) + (e << 23));
}

// ---------------- GEMM C = alpha * A * B^T (+bias) ----------------
// A: [M,K] row-major, B: [N,K] row-major. 128x128 tile, Kc=8, 256 threads, 8x8 micro.
// HEAD_STORE=1 remaps C[m,n] (m=b*S+s, n=h*64+d) into head-major [B,H,S,DK].
template <int HEAD_STORE>
__global__ void __launch_bounds__(256) gemm_nt_kernel(
    const float* __restrict__ A, const float* __restrict__ Bm,
    const float* __restrict__ bias, float* __restrict__ C,
    int M, int N, int K, float alpha,
    int batchStrideA, int batchStrideB, long long batchStrideC)
{
    const int bm = blockIdx.y * 128;
    const int bn = blockIdx.x * 128;
    const int bz = blockIdx.z;
    A  += (size_t)bz * batchStrideA;
    Bm += (size_t)bz * batchStrideB;
    C  += (size_t)bz * batchStrideC;

    __shared__ float sA[8][128];
    __shared__ float sB[8][128];

    const int t  = threadIdx.x;
    const int lr = t >> 1;          // 0..127 row within tile
    const int lk = (t & 1) * 4;     // 0 or 4 within k-chunk
    const int ty = t >> 4;          // 0..15
    const int tx = t & 15;          // 0..15

    float acc[8][8];
    #pragma unroll
    for (int i = 0; i < 8; i++)
        #pragma unroll
        for (int j = 0; j < 8; j++) acc[i][j] = 0.f;

    for (int k0 = 0; k0 < K; k0 += 8) {
        float4 av = *reinterpret_cast<const float4*>(&A [(size_t)(bm + lr) * K + k0 + lk]);
        float4 bv = *reinterpret_cast<const float4*>(&Bm[(size_t)(bn + lr) * K + k0 + lk]);
        __syncthreads();
        sA[lk + 0][lr] = av.x; sA[lk + 1][lr] = av.y;
        sA[lk + 2][lr] = av.z; sA[lk + 3][lr] = av.w;
        sB[lk + 0][lr] = bv.x; sB[lk + 1][lr] = bv.y;
        sB[lk + 2][lr] = bv.z; sB[lk + 3][lr] = bv.w;
        __syncthreads();
        #pragma unroll
        for (int kk = 0; kk < 8; kk++) {
            float4 a0 = *reinterpret_cast<const float4*>(&sA[kk][ty * 8]);
            float4 a1 = *reinterpret_cast<const float4*>(&sA[kk][ty * 8 + 4]);
            float4 b0 = *reinterpret_cast<const float4*>(&sB[kk][tx * 8]);
            float4 b1 = *reinterpret_cast<const float4*>(&sB[kk][tx * 8 + 4]);
            float a[8] = {a0.x, a0.y, a0.z, a0.w, a1.x, a1.y, a1.z, a1.w};
            float b[8] = {b0.x, b0.y, b0.z, b0.w, b1.x, b1.y, b1.z, b1.w};
            #pragma unroll
            for (int i = 0; i < 8; i++)
                #pragma unroll
                for (int j = 0; j < 8; j++)
                    acc[i][j] = fmaf(a[i], b[j], acc[i][j]);
        }
    }

    #pragma unroll
    for (int i = 0; i < 8; i++) {
        const int m = bm + ty * 8 + i;
        #pragma unroll
        for (int j = 0; j < 8; j++) {
            const int n = bn + tx * 8 + j;
            float v = acc[i][j] * alpha;
            if (bias) v += bias[n];
            if (HEAD_STORE) {
                const int b = m >> 10, s = m & 1023;
                const int h = n >> 6,  d = n & 63;
                C[(((size_t)(b * Hn + h) * Sn) + s) * DKn + d] = v;
            } else {
                C[(size_t)m * N + n] = v;
            }
        }
    }
}

// ---------------- softmax both streams + elementwise-max merge ----------------
// One block per (b,h,q) row. Writes merged P in-place into Sr.
__global__ void __launch_bounds__(256) softmax_max_kernel(
    const float* __restrict__ Sr, const float* __restrict__ Sf, float* __restrict__ P)
{
    __shared__ float sred[8];
    const size_t row = blockIdx.x;
    const int t = threadIdx.x;

    float4 xr = reinterpret_cast<const float4*>(Sr + row * Sn)[t];
    float4 xf = reinterpret_cast<const float4*>(Sf + row * Sn)[t];

    // ---- stream r: max ----
    float m = fmaxf(fmaxf(xr.x, xr.y), fmaxf(xr.z, xr.w));
    #pragma unroll
    for (int o = 16; o; o >>= 1) m = fmaxf(m, __shfl_xor_sync(0xffffffffu, m, o));
    if ((t & 31) == 0) sred[t >> 5] = m;
    __syncthreads();
    m = sred[0];
    #pragma unroll
    for (int i = 1; i < 8; i++) m = fmaxf(m, sred[i]);

    float er0 = fexp(xr.x - m), er1 = fexp(xr.y - m);
    float er2 = fexp(xr.z - m), er3 = fexp(xr.w - m);
    float s = er0 + er1 + er2 + er3;
    #pragma unroll
    for (int o = 16; o; o >>= 1) s += __shfl_xor_sync(0xffffffffu, s, o);
    __syncthreads();
    if ((t & 31) == 0) sred[t >> 5] = s;
    __syncthreads();
    s = sred[0];
    #pragma unroll
    for (int i = 1; i < 8; i++) s += sred[i];
    const float invZr = 1.0f / s;

    // ---- stream f: max ----
    float mf = fmaxf(fmaxf(xf.x, xf.y), fmaxf(xf.z, xf.w));
    #pragma unroll
    for (int o = 16; o; o >>= 1) mf = fmaxf(mf, __shfl_xor_sync(0xffffffffu, mf, o));
    __syncthreads();
    if ((t & 31) == 0) sred[t >> 5] = mf;
    __syncthreads();
    mf = sred[0];
    #pragma unroll
    for (int i = 1; i < 8; i++) mf = fmaxf(mf, sred[i]);

    float ef0 = fexp(xf.x - mf), ef1 = fexp(xf.y - mf);
    float ef2 = fexp(xf.z - mf), ef3 = fexp(xf.w - mf);
    float sf = ef0 + ef1 + ef2 + ef3;
    #pragma unroll
    for (int o = 16; o; o >>= 1) sf += __shfl_xor_sync(0xffffffffu, sf, o);
    __syncthreads();
    if ((t & 31) == 0) sred[t >> 5] = sf;
    __syncthreads();
    sf = sred[0];
    #pragma unroll
    for (int i = 1; i < 8; i++) sf += sred[i];
    const float invZf = 1.0f / sf;

    float4 p;
    p.x = fmaxf(er0 * invZr, ef0 * invZf);
    p.y = fmaxf(er1 * invZr, ef1 * invZf);
    p.z = fmaxf(er2 * invZr, ef2 * invZf);
    p.w = fmaxf(er3 * invZr, ef3 * invZf);
    reinterpret_cast<float4*>(P + row * Sn)[t] = p;
}

// ---------------- PV: Cr = P @ Vr, Cf = P @ Vf (P read once) ----------------
// Per block: 128 q-rows x 64 cols, K-chunks of 16. Stores into [B,S,H*64+d] layout.
__global__ void __launch_bounds__(256) pv_kernel(
    const float* __restrict__ P, const float* __restrict__ Vr,
    const float* __restrict__ Vf, float* __restrict__ Cr, float* __restrict__ Cf)
{
    const int bh = blockIdx.z;
    const int b = bh >> 3, h = bh & 7;
    const int q0 = blockIdx.x * 128;

    const float* Pb  = P  + (size_t)bh * Sn * Sn + (size_t)q0 * Sn;
    const float* Vrb = Vr + (size_t)bh * Sn * DKn;
    const float* Vfb = Vf + (size_t)bh * Sn * DKn;

    __shared__ float sP[16][128];
    __shared__ float sVr[16][64];
    __shared__ float sVf[16][64];

    const int t = threadIdx.x;
    const int pr = t >> 1;            // 0..127
    const int pk = (t & 1) * 8;       // 0 or 8
    const int vrow = t >> 4;          // 0..15
    const int vcol = (t & 15) * 4;    // 0..60
    const int ty = t >> 4;            // 0..15 -> 8 q-rows each
    const int tx = t & 15;            // 0..15 -> 4 cols each

    float ar[8][4], af[8][4];
    #pragma unroll
    for (int i = 0; i < 8; i++)
        #pragma unroll
        for (int j = 0; j < 4; j++) { ar[i][j] = 0.f; af[i][j] = 0.f; }

    for (int k0 = 0; k0 < Sn; k0 += 16) {
        float4 p0 = *reinterpret_cast<const float4*>(&Pb [(size_t)pr * Sn + k0 + pk]);
        float4 p1 = *reinterpret_cast<const float4*>(&Pb [(size_t)pr * Sn + k0 + pk + 4]);
        float4 v0 = *reinterpret_cast<const float4*>(&Vrb[(size_t)(k0 + vrow) * DKn + vcol]);
        float4 v1 = *reinterpret_cast<const float4*>(&Vfb[(size_t)(k0 + vrow) * DKn + vcol]);
        __syncthreads();
        sP[pk + 0][pr] = p0.x; sP[pk + 1][pr] = p0.y;
        sP[pk + 2][pr] = p0.z; sP[pk + 3][pr] = p0.w;
        sP[pk + 4][pr] = p1.x; sP[pk + 5][pr] = p1.y;
        sP[pk + 6][pr] = p1.z; sP[pk + 7][pr] = p1.w;
        *reinterpret_cast<float4*>(&sVr[vrow][vcol]) = v0;
        *reinterpret_cast<float4*>(&sVf[vrow][vcol]) = v1;
        __syncthreads();
        #pragma unroll
        for (int kk = 0; kk < 16; kk++) {
            float4 pa = *reinterpret_cast<const float4*>(&sP[kk][ty * 8]);
            float4 pb = *reinterpret_cast<const float4*>(&sP[kk][ty * 8 + 4]);
            float p[8] = {pa.x, pa.y, pa.z, pa.w, pb.x, pb.y, pb.z, pb.w};
            float4 vr4 = *reinterpret_cast<const float4*>(&sVr[kk][tx * 4]);
            float4 vf4 = *reinterpret_cast<const float4*>(&sVf[kk][tx * 4]);
            float vrv[4] = {vr4.x, vr4.y, vr4.z, vr4.w};
            float vfv[4] = {vf4.x, vf4.y, vf4.z, vf4.w};
            #pragma unroll
            for (int i = 0; i < 8; i++)
                #pragma unroll
                for (int j = 0; j < 4; j++) {
                    ar[i][j] = fmaf(p[i], vrv[j], ar[i][j]);
                    af[i][j] = fmaf(p[i], vfv[j], af[i][j]);
                }
        }
    }

    #pragma unroll
    for (int i = 0; i < 8; i++) {
        const int q = q0 + ty * 8 + i;
        #pragma unroll
        for (int j = 0; j < 4; j++) {
            const int d = tx * 4 + j;
            Cr[((size_t)b * Sn + q) * DMn + h * DKn + d] = ar[i][j];
            Cf[((size_t)b * Sn + q) * DMn + h * DKn + d] = af[i][j];
        }
    }
}

// ---------------- host ----------------
extern "C" void kernel_launch(void* const* d_in, const int* in_sizes, int n_in,
                              void* d_out, int out_size)
{
    const float* x_rgb  = (const float*)d_in[0];
    const float* x_flow = (const float*)d_in[1];
    const float* Wq1 = (const float*)d_in[2];  const float* bq1 = (const float*)d_in[3];
    const float* Wk1 = (const float*)d_in[4];  const float* bk1 = (const float*)d_in[5];
    const float* Wv1 = (const float*)d_in[6];  const float* bv1 = (const float*)d_in[7];
    const float* Wq2 = (const float*)d_in[8];  const float* bq2 = (const float*)d_in[9];
    const float* Wk2 = (const float*)d_in[10]; const float* bk2 = (const float*)d_in[11];
    const float* Wv2 = (const float*)d_in[12]; const float* bv2 = (const float*)d_in[13];
    const float* Wo1 = (const float*)d_in[14]; const float* bo1 = (const float*)d_in[15];
    const float* Wo2 = (const float*)d_in[16]; const float* bo2 = (const float*)d_in[17];
    float* out = (float*)d_out;

    float *Qr, *Kr, *Vr, *Qf, *Kf, *Vf, *Sr, *Sf, *Cr, *Cf;
    cudaGetSymbolAddress((void**)&Qr, g_Qr);
    cudaGetSymbolAddress((void**)&Kr, g_Kr);
    cudaGetSymbolAddress((void**)&Vr, g_Vr);
    cudaGetSymbolAddress((void**)&Qf, g_Qf);
    cudaGetSymbolAddress((void**)&Kf, g_Kf);
    cudaGetSymbolAddress((void**)&Vf, g_Vf);
    cudaGetSymbolAddress((void**)&Sr, g_Sr);
    cudaGetSymbolAddress((void**)&Sf, g_Sf);
    cudaGetSymbolAddress((void**)&Cr, g_Cr);
    cudaGetSymbolAddress((void**)&Cf, g_Cf);

    const dim3 blk(256);

    // 1) six input projections -> head-major [B,H,S,DK]
    const dim3 gProj(DMn / 128, MROWS / 128, 1);
    gemm_nt_kernel<1><<<gProj, blk>>>(x_rgb,  Wq1, bq1, Qr, MROWS, DMn, DMn, 1.f, 0, 0, 0);
    gemm_nt_kernel<1><<<gProj, blk>>>(x_rgb,  Wk1, bk1, Kr, MROWS, DMn, DMn, 1.f, 0, 0, 0);
    gemm_nt_kernel<1><<<gProj, blk>>>(x_rgb,  Wv1, bv1, Vr, MROWS, DMn, DMn, 1.f, 0, 0, 0);
    gemm_nt_kernel<1><<<gProj, blk>>>(x_flow, Wq2, bq2, Qf, MROWS, DMn, DMn, 1.f, 0, 0, 0);
    gemm_nt_kernel<1><<<gProj, blk>>>(x_flow, Wk2, bk2, Kf, MROWS, DMn, DMn, 1.f, 0, 0, 0);
    gemm_nt_kernel<1><<<gProj, blk>>>(x_flow, Wv2, bv2, Vf, MROWS, DMn, DMn, 1.f, 0, 0, 0);

    // 2) batched scores S = (Q K^T) * 1/sqrt(dk), per (b,h)
    const dim3 gScore(Sn / 128, Sn / 128, Bn * Hn);
    gemm_nt_kernel<0><<<gScore, blk>>>(Qr, Kr, nullptr, Sr, Sn, Sn, DKn, 0.125f,
                                       Sn * DKn, Sn * DKn, (long long)Sn * Sn);
    gemm_nt_kernel<0><<<gScore, blk>>>(Qf, Kf, nullptr, Sf, Sn, Sn, DKn, 0.125f,
                                       Sn * DKn, Sn * DKn, (long long)Sn * Sn);

    // 3) softmax each stream + max merge (in place into Sr)
    softmax_max_kernel<<<Bn * Hn * Sn, 256>>>(Sr, Sf, Sr);

    // 4) PV for both streams (P read once), contexts in [B,S,D_MODEL]
    const dim3 gPV(Sn / 128, 1, Bn * Hn);
    pv_kernel<<<gPV, blk>>>(Sr, Vr, Vf, Cr, Cf);

    // 5) output projections -> concatenated outputs
    const dim3 gOut(DMn / 128, MROWS / 128, 1);
    gemm_nt_kernel<0><<<gOut, blk>>>(Cr, Wo1, bo1, out, MROWS, DMn, DMn, 1.f, 0, 0, 0);
    gemm_nt_kernel<0><<<gOut, blk>>>(Cf, Wo2, bo2, out + (size_t)MROWS * DMn,
                                     MROWS, DMn, DMn, 1.f, 0, 0, 0);
}

// round 3
// speedup vs baseline: 2.3452x; 2.3452x over previous
#include <cuda_runtime.h>
#include <cuda_bf16.h>
#include <stdint.h>
#include <math.h>

#define Bn 8
#define Hn 8
#define Sn 1024
#define DMn 512
#define DKn 64
#define MROWS (Bn * Sn)   // 8192

// ---------------- scratch (device globals; no runtime allocation) ----------------
__device__ float g_Qr[Bn * Hn * Sn * DKn];
__device__ float g_Kr[Bn * Hn * Sn * DKn];
__device__ float g_Vr[Bn * Hn * DKn * Sn];   // TRANSPOSED: [b,h,d,s]
__device__ float g_Qf[Bn * Hn * Sn * DKn];
__device__ float g_Kf[Bn * Hn * Sn * DKn];
__device__ float g_Vf[Bn * Hn * DKn * Sn];   // TRANSPOSED: [b,h,d,s]
__device__ float g_Sr[(size_t)Bn * Hn * Sn * Sn];   // 256 MB; reused for merged P
__device__ float g_Sf[(size_t)Bn * Hn * Sn * Sn];
__device__ float g_Cr[MROWS * DMn];
__device__ float g_Cf[MROWS * DMn];

// ---------------- smem layout ----------------
// bf16 tiles (rows of 64B = 32 bf16): AHI @0, ALO @8K, BHI @16K, BLO @24K  (32KB)
// epilogue stage: float sC[64][132] from 0 (33792 B)
#define T_AHI 0
#define T_ALO 8192
#define T_BHI 16384
#define T_BLO 24576
#define SMEM_BYTES 33792

// ---------------- helpers ----------------
__device__ __forceinline__ uint32_t bfpair(__nv_bfloat16 a, __nv_bfloat16 b) {
    __nv_bfloat162 t = __halves2bfloat162(a, b);
    return *reinterpret_cast<uint32_t*>(&t);
}

// split float8 (x = cols c..c+3, y = cols c+8..c+11) into hi/lo uint4 in the
// interleaved physical order: [x01, y01, x23, y23]
__device__ __forceinline__ void split8(const float4& x, const float4& y,
                                       uint4& hi, uint4& lo) {
    __nv_bfloat16 hx0 = __float2bfloat16_rn(x.x), hx1 = __float2bfloat16_rn(x.y);
    __nv_bfloat16 hx2 = __float2bfloat16_rn(x.z), hx3 = __float2bfloat16_rn(x.w);
    __nv_bfloat16 hy0 = __float2bfloat16_rn(y.x), hy1 = __float2bfloat16_rn(y.y);
    __nv_bfloat16 hy2 = __float2bfloat16_rn(y.z), hy3 = __float2bfloat16_rn(y.w);
    hi.x = bfpair(hx0, hx1);
    hi.y = bfpair(hy0, hy1);
    hi.z = bfpair(hx2, hx3);
    hi.w = bfpair(hy2, hy3);
    lo.x = bfpair(__float2bfloat16_rn(x.x - __bfloat162float(hx0)),
                  __float2bfloat16_rn(x.y - __bfloat162float(hx1)));
    lo.y = bfpair(__float2bfloat16_rn(y.x - __bfloat162float(hy0)),
                  __float2bfloat16_rn(y.y - __bfloat162float(hy1)));
    lo.z = bfpair(__float2bfloat16_rn(x.z - __bfloat162float(hx2)),
                  __float2bfloat16_rn(x.w - __bfloat162float(hx3)));
    lo.w = bfpair(__float2bfloat16_rn(y.z - __bfloat162float(hy2)),
                  __float2bfloat16_rn(y.w - __bfloat162float(hy3)));
}

#define MMA(c, a, b) \
    asm volatile( \
        "mma.sync.aligned.m16n8k16.row.col.f32.bf16.bf16.f32 " \
        "{%0,%1,%2,%3},{%4,%5,%6,%7},{%8,%9},{%0,%1,%2,%3};" \
        : "+f"((c)[0]), "+f"((c)[1]), "+f"((c)[2]), "+f"((c)[3]) \
        : "r"((a)[0]), "r"((a)[1]), "r"((a)[2]), "r"((a)[3]), \
          "r"((b)[0]), "r"((b)[1]))

// ============ GEMM: C = alpha * A * B^T (+bias). A:[M,K], B:[N,K] row-major ============
// 128x128 block tile, Kc=32, bf16 mma.sync with 3-pass fp32-split.
// SMODE: 0 plain C (ldc=N), 1 head-major [B,H,S,DK], 2 V-transposed [B,H,DK,S], 3 PV split
// DUALB: B rows 0..63 from B0, 64..127 from B1 (both [64,K])
template <int SMODE, int DUALB>
__global__ void __launch_bounds__(256, 2) mma_gemm(
    const float* __restrict__ A, const float* __restrict__ B0,
    const float* __restrict__ B1, const float* __restrict__ bias,
    float* __restrict__ C0, float* __restrict__ C1,
    int N, int K, float alpha,
    long long strideA, long long strideB, long long strideC)
{
    extern __shared__ char smem[];
    const int tid = threadIdx.x;
    const int w = tid >> 5, lane = tid & 31;
    const int wm = w >> 2, wn = w & 3;
    const int g = lane >> 2, tig = lane & 3;
    const int bm = blockIdx.y * 128, bn = blockIdx.x * 128;
    const int z = blockIdx.z;
    A += (size_t)z * strideA;
    const float* Bp0 = B0 + (size_t)z * strideB;
    const float* Bp1 = DUALB ? (B1 + (size_t)z * strideB) : B0;
    C0 += (SMODE == 0) ? (size_t)z * strideC : 0;

    float acc[4][4][4];
    #pragma unroll
    for (int i = 0; i < 4; i++)
        #pragma unroll
        for (int j = 0; j < 4; j++)
            #pragma unroll
            for (int c = 0; c < 4; c++) acc[i][j][c] = 0.f;

    // producer constants: thread -> (row pr / pr+64, k-sub position)
    const int pr = tid >> 2;                   // 0..63
    const int pc = tid & 3;
    const int ps = pc >> 1, pq = pc & 1;       // k panel, quarter
    const int kcol = ps * 16 + pq * 4;         // first float4 col (second at +8)
    const uint32_t stsOff = (uint32_t)(((ps * 32 + pq * 16) ^ ((pr & 2) << 4)));

    const int nchunks = K >> 5;
    for (int cc = 0; cc < nchunks; cc++) {
        const int k0 = cc << 5;
        if (cc) __syncthreads();
        #pragma unroll
        for (int it = 0; it < 2; it++) {
            const int r = pr + it * 64;
            // ---- A ----
            {
                const float* p = A + (size_t)(bm + r) * K + k0 + kcol;
                float4 x = *reinterpret_cast<const float4*>(p);
                float4 y = *reinterpret_cast<const float4*>(p + 8);
                uint4 hi, lo;
                split8(x, y, hi, lo);
                *reinterpret_cast<uint4*>(smem + T_AHI + r * 64 + stsOff) = hi;
                *reinterpret_cast<uint4*>(smem + T_ALO + r * 64 + stsOff) = lo;
            }
            // ---- B ----
            {
                const float* p;
                if (DUALB)
                    p = (r < 64 ? Bp0 + (size_t)r * K : Bp1 + (size_t)(r - 64) * K) + k0 + kcol;
                else
                    p = Bp0 + (size_t)(bn + r) * K + k0 + kcol;
                float4 x = *reinterpret_cast<const float4*>(p);
                float4 y = *reinterpret_cast<const float4*>(p + 8);
                uint4 hi, lo;
                split8(x, y, hi, lo);
                *reinterpret_cast<uint4*>(smem + T_BHI + r * 64 + stsOff) = hi;
                *reinterpret_cast<uint4*>(smem + T_BLO + r * 64 + stsOff) = lo;
            }
        }
        __syncthreads();

        #pragma unroll
        for (int s = 0; s < 2; s++) {
            uint32_t bh[4][2], bl[4][2], Af[4][4];
            #pragma unroll
            for (int j = 0; j < 4; j++) {
                const int rB = wn * 32 + j * 8 + g;
                const uint32_t co = (uint32_t)((s * 32 + tig * 8) ^ ((rB & 2) << 4)) + rB * 64;
                uint2 u = *reinterpret_cast<const uint2*>(smem + T_BHI + co);
                bh[j][0] = u.x; bh[j][1] = u.y;
                uint2 v = *reinterpret_cast<const uint2*>(smem + T_BLO + co);
                bl[j][0] = v.x; bl[j][1] = v.y;
            }
            #pragma unroll
            for (int i = 0; i < 4; i++) {
                const int r0 = wm * 64 + i * 16 + g;
                const uint32_t co = (uint32_t)((s * 32 + tig * 8) ^ ((r0 & 2) << 4));
                uint2 u = *reinterpret_cast<const uint2*>(smem + T_AHI + r0 * 64 + co);
                uint2 v = *reinterpret_cast<const uint2*>(smem + T_AHI + (r0 + 8) * 64 + co);
                Af[i][0] = u.x; Af[i][1] = v.x; Af[i][2] = u.y; Af[i][3] = v.y;
            }
            #pragma unroll
            for (int i = 0; i < 4; i++)
                #pragma unroll
                for (int j = 0; j < 4; j++) MMA(acc[i][j], Af[i], bh[j]);
            #pragma unroll
            for (int i = 0; i < 4; i++)
                #pragma unroll
                for (int j = 0; j < 4; j++) MMA(acc[i][j], Af[i], bl[j]);
            #pragma unroll
            for (int i = 0; i < 4; i++) {
                const int r0 = wm * 64 + i * 16 + g;
                const uint32_t co = (uint32_t)((s * 32 + tig * 8) ^ ((r0 & 2) << 4));
                uint2 u = *reinterpret_cast<const uint2*>(smem + T_ALO + r0 * 64 + co);
                uint2 v = *reinterpret_cast<const uint2*>(smem + T_ALO + (r0 + 8) * 64 + co);
                Af[i][0] = u.x; Af[i][1] = v.x; Af[i][2] = u.y; Af[i][3] = v.y;
            }
            #pragma unroll
            for (int i = 0; i < 4; i++)
                #pragma unroll
                for (int j = 0; j < 4; j++) MMA(acc[i][j], Af[i], bh[j]);
        }
    }
    __syncthreads();

    // ---- epilogue: two 64-row halves through smem stage ----
    float* sC = reinterpret_cast<float*>(smem);
    #pragma unroll
    for (int hh = 0; hh < 2; hh++) {
        if (wm == hh) {
            #pragma unroll
            for (int i = 0; i < 4; i++) {
                const int rl = i * 16 + g;
                #pragma unroll
                for (int j = 0; j < 4; j++) {
                    const int cl = wn * 32 + j * 8 + 2 * tig;
                    float bv0 = 0.f, bv1 = 0.f;
                    if (bias) { bv0 = __ldg(bias + bn + cl); bv1 = __ldg(bias + bn + cl + 1); }
                    float2 v0 = make_float2(acc[i][j][0] * alpha + bv0,
                                            acc[i][j][1] * alpha + bv1);
                    float2 v1 = make_float2(acc[i][j][2] * alpha + bv0,
                                            acc[i][j][3] * alpha + bv1);
                    *reinterpret_cast<float2*>(&sC[rl * 132 + cl]) = v0;
                    *reinterpret_cast<float2*>(&sC[(rl + 8) * 132 + cl]) = v1;
                }
            }
        }
        __syncthreads();

        const int mbase = bm + hh * 64;
        if (SMODE == 0) {
            for (int e = tid * 4; e < 64 * 128; e += 1024) {
                const int row = e >> 7, col = e & 127;
                float4 v = make_float4(sC[row * 132 + col],     sC[row * 132 + col + 1],
                                       sC[row * 132 + col + 2], sC[row * 132 + col + 3]);
                *reinterpret_cast<float4*>(&C0[(size_t)(mbase + row) * N + bn + col]) = v;
            }
        } else if (SMODE == 1) {
            const int b = mbase >> 10, s0 = mbase & 1023, h0 = bn >> 6;
            for (int e = tid * 4; e < 64 * 128; e += 1024) {
                const int row = e >> 7, col = e & 127;
                const int hd = col >> 6, d = col & 63;
                float4 v = make_float4(sC[row * 132 + col],     sC[row * 132 + col + 1],
                                       sC[row * 132 + col + 2], sC[row * 132 + col + 3]);
                *reinterpret_cast<float4*>(
                    &C0[(((size_t)(b * Hn + h0 + hd)) * Sn + s0 + row) * DKn + d]) = v;
            }
        } else if (SMODE == 2) {
            const int b = mbase >> 10, s0 = mbase & 1023, h0 = bn >> 6;
            for (int e = tid * 4; e < 64 * 128; e += 1024) {
                const int c = e >> 6, sl = e & 63;
                float4 v = make_float4(sC[(sl + 0) * 132 + c], sC[(sl + 1) * 132 + c],
                                       sC[(sl + 2) * 132 + c], sC[(sl + 3) * 132 + c]);
                *reinterpret_cast<float4*>(
                    &C0[(((size_t)(b * Hn + h0 + (c >> 6))) * DKn + (c & 63)) * Sn + s0 + sl]) = v;
            }
        } else {  // SMODE == 3: PV split store
            const int b = z >> 3, hd = z & 7;
            for (int e = tid * 4; e < 64 * 128; e += 1024) {
                const int row = e >> 7, col = e & 127;
                const int d = col & 63;
                float4 v = make_float4(sC[row * 132 + col],     sC[row * 132 + col + 1],
                                       sC[row * 132 + col + 2], sC[row * 132 + col + 3]);
                float* dst = (col < 64) ? C0 : C1;
                *reinterpret_cast<float4*>(
                    &dst[((size_t)b * Sn + mbase + row) * DMn + hd * DKn + d]) = v;
            }
        }
        __syncthreads();
    }
}

// ---------------- fast exp ----------------
__device__ __forceinline__ float fexp(float x) {
    float t  = x * 1.4426950408889634f;
    float fi = rintf(t);
    float f  = t - fi;
    float p  = 1.3333558146428443e-3f;
    p = fmaf(p, f, 9.6181291076284770e-3f);
    p = fmaf(p, f, 5.5504108664821580e-2f);
    p = fmaf(p, f, 2.4022650695910072e-1f);
    p = fmaf(p, f, 6.9314718055994531e-1f);
    p = fmaf(p, f, 1.0f);
    int e = (int)fi;
    return __int_as_float(__float_as_int(p) + (e << 23));
}

// ---------------- softmax both streams + elementwise-max merge ----------------
__global__ void __launch_bounds__(256) softmax_max_kernel(
    const float* __restrict__ Sr, const float* __restrict__ Sf, float* __restrict__ P)
{
    __shared__ float sred[8];
    const size_t row = blockIdx.x;
    const int t = threadIdx.x;

    float4 xr = reinterpret_cast<const float4*>(Sr + row * Sn)[t];
    float4 xf = reinterpret_cast<const float4*>(Sf + row * Sn)[t];

    float m = fmaxf(fmaxf(xr.x, xr.y), fmaxf(xr.z, xr.w));
    #pragma unroll
    for (int o = 16; o; o >>= 1) m = fmaxf(m, __shfl_xor_sync(0xffffffffu, m, o));
    if ((t & 31) == 0) sred[t >> 5] = m;
    __syncthreads();
    m = sred[0];
    #pragma unroll
    for (int i = 1; i < 8; i++) m = fmaxf(m, sred[i]);

    float er0 = fexp(xr.x - m), er1 = fexp(xr.y - m);
    float er2 = fexp(xr.z - m), er3 = fexp(xr.w - m);
    float s = er0 + er1 + er2 + er3;
    #pragma unroll
    for (int o = 16; o; o >>= 1) s += __shfl_xor_sync(0xffffffffu, s, o);
    __syncthreads();
    if ((t & 31) == 0) sred[t >> 5] = s;
    __syncthreads();
    s = sred[0];
    #pragma unroll
    for (int i = 1; i < 8; i++) s += sred[i];
    const float invZr = 1.0f / s;

    float mf = fmaxf(fmaxf(xf.x, xf.y), fmaxf(xf.z, xf.w));
    #pragma unroll
    for (int o = 16; o; o >>= 1) mf = fmaxf(mf, __shfl_xor_sync(0xffffffffu, mf, o));
    __syncthreads();
    if ((t & 31) == 0) sred[t >> 5] = mf;
    __syncthreads();
    mf = sred[0];
    #pragma unroll
    for (int i = 1; i < 8; i++) mf = fmaxf(mf, sred[i]);

    float ef0 = fexp(xf.x - mf), ef1 = fexp(xf.y - mf);
    float ef2 = fexp(xf.z - mf), ef3 = fexp(xf.w - mf);
    float sf = ef0 + ef1 + ef2 + ef3;
    #pragma unroll
    for (int o = 16; o; o >>= 1) sf += __shfl_xor_sync(0xffffffffu, sf, o);
    __syncthreads();
    if ((t & 31) == 0) sred[t >> 5] = sf;
    __syncthreads();
    sf = sred[0];
    #pragma unroll
    for (int i = 1; i < 8; i++) sf += sred[i];
    const float invZf = 1.0f / sf;

    float4 p;
    p.x = fmaxf(er0 * invZr, ef0 * invZf);
    p.y = fmaxf(er1 * invZr, ef1 * invZf);
    p.z = fmaxf(er2 * invZr, ef2 * invZf);
    p.w = fmaxf(er3 * invZr, ef3 * invZf);
    reinterpret_cast<float4*>(P + row * Sn)[t] = p;
}

// ---------------- host ----------------
extern "C" void kernel_launch(void* const* d_in, const int* in_sizes, int n_in,
                              void* d_out, int out_size)
{
    const float* x_rgb  = (const float*)d_in[0];
    const float* x_flow = (const float*)d_in[1];
    const float* Wq1 = (const float*)d_in[2];  const float* bq1 = (const float*)d_in[3];
    const float* Wk1 = (const float*)d_in[4];  const float* bk1 = (const float*)d_in[5];
    const float* Wv1 = (const float*)d_in[6];  const float* bv1 = (const float*)d_in[7];
    const float* Wq2 = (const float*)d_in[8];  const float* bq2 = (const float*)d_in[9];
    const float* Wk2 = (const float*)d_in[10]; const float* bk2 = (const float*)d_in[11];
    const float* Wv2 = (const float*)d_in[12]; const float* bv2 = (const float*)d_in[13];
    const float* Wo1 = (const float*)d_in[14]; const float* bo1 = (const float*)d_in[15];
    const float* Wo2 = (const float*)d_in[16]; const float* bo2 = (const float*)d_in[17];
    float* out = (float*)d_out;

    float *Qr, *Kr, *Vr, *Qf, *Kf, *Vf, *Sr, *Sf, *Cr, *Cf;
    cudaGetSymbolAddress((void**)&Qr, g_Qr);
    cudaGetSymbolAddress((void**)&Kr, g_Kr);
    cudaGetSymbolAddress((void**)&Vr, g_Vr);
    cudaGetSymbolAddress((void**)&Qf, g_Qf);
    cudaGetSymbolAddress((void**)&Kf, g_Kf);
    cudaGetSymbolAddress((void**)&Vf, g_Vf);
    cudaGetSymbolAddress((void**)&Sr, g_Sr);
    cudaGetSymbolAddress((void**)&Sf, g_Sf);
    cudaGetSymbolAddress((void**)&Cr, g_Cr);
    cudaGetSymbolAddress((void**)&Cf, g_Cf);

    cudaFuncSetAttribute((const void*)mma_gemm<0,0>, cudaFuncAttributeMaxDynamicSharedMemorySize, SMEM_BYTES);
    cudaFuncSetAttribute((const void*)mma_gemm<1,0>, cudaFuncAttributeMaxDynamicSharedMemorySize, SMEM_BYTES);
    cudaFuncSetAttribute((const void*)mma_gemm<2,0>, cudaFuncAttributeMaxDynamicSharedMemorySize, SMEM_BYTES);
    cudaFuncSetAttribute((const void*)mma_gemm<3,1>, cudaFuncAttributeMaxDynamicSharedMemorySize, SMEM_BYTES);

    const dim3 blk(256);

    // 1) projections (M=8192, N=512, K=512)
    const dim3 gP(DMn / 128, MROWS / 128, 1);
    mma_gemm<1,0><<<gP, blk, SMEM_BYTES>>>(x_rgb,  Wq1, nullptr, bq1, Qr, nullptr, DMn, DMn, 1.f, 0, 0, 0);
    mma_gemm<1,0><<<gP, blk, SMEM_BYTES>>>(x_rgb,  Wk1, nullptr, bk1, Kr, nullptr, DMn, DMn, 1.f, 0, 0, 0);
    mma_gemm<2,0><<<gP, blk, SMEM_BYTES>>>(x_rgb,  Wv1, nullptr, bv1, Vr, nullptr, DMn, DMn, 1.f, 0, 0, 0);
    mma_gemm<1,0><<<gP, blk, SMEM_BYTES>>>(x_flow, Wq2, nullptr, bq2, Qf, nullptr, DMn, DMn, 1.f, 0, 0, 0);
    mma_gemm<1,0><<<gP, blk, SMEM_BYTES>>>(x_flow, Wk2, nullptr, bk2, Kf, nullptr, DMn, DMn, 1.f, 0, 0, 0);
    mma_gemm<2,0><<<gP, blk, SMEM_BYTES>>>(x_flow, Wv2, nullptr, bv2, Vf, nullptr, DMn, DMn, 1.f, 0, 0, 0);

    // 2) scores S = (Q K^T)/8, batched over b*h (M=N=1024, K=64)
    const dim3 gS(Sn / 128, Sn / 128, Bn * Hn);
    mma_gemm<0,0><<<gS, blk, SMEM_BYTES>>>(Qr, Kr, nullptr, nullptr, Sr, nullptr, Sn, DKn, 0.125f,
                                           (long long)Sn * DKn, (long long)Sn * DKn, (long long)Sn * Sn);
    mma_gemm<0,0><<<gS, blk, SMEM_BYTES>>>(Qf, Kf, nullptr, nullptr, Sf, nullptr, Sn, DKn, 0.125f,
                                           (long long)Sn * DKn, (long long)Sn * DKn, (long long)Sn * Sn);

    // 3) softmax + max merge (in place into Sr)
    softmax_max_kernel<<<Bn * Hn * Sn, 256>>>(Sr, Sf, Sr);

    // 4) PV both streams in one GEMM (N=128 = [Vr | Vf]), K=1024
    mma_gemm<3,1><<<dim3(1, Sn / 128, Bn * Hn), blk, SMEM_BYTES>>>(
        Sr, Vr, Vf, nullptr, Cr, Cf, 128, Sn, 1.f,
        (long long)Sn * Sn, (long long)DKn * Sn, 0);

    // 5) output projections (M=8192, N=512, K=512)
    const dim3 gO(DMn / 128, MROWS / 128, 1);
    mma_gemm<0,0><<<gO, blk, SMEM_BYTES>>>(Cr, Wo1, nullptr, bo1, out, nullptr, DMn, DMn, 1.f, 0, 0, 0);
    mma_gemm<0,0><<<gO, blk, SMEM_BYTES>>>(Cf, Wo2, nullptr, bo2, out + (size_t)MROWS * DMn, nullptr,
                                           DMn, DMn, 1.f, 0, 0, 0);
}

// round 6
// speedup vs baseline: 2.4238x; 1.0335x over previous
#include <cuda_runtime.h>
#include <cuda_bf16.h>
#include <stdint.h>
#include <math.h>

#define Bn 8
#define Hn 8
#define Sn 1024
#define DMn 512
#define DKn 64
#define MROWS (Bn * Sn)   // 8192

// ---------------- scratch (device globals; no runtime allocation) ----------------
// split operands stored as uint32 pairs (2 bf16) in per-32k-chunk interleaved order
__device__ uint32_t g_xrh[MROWS * 256], g_xrl[MROWS * 256];
__device__ uint32_t g_xfh[MROWS * 256], g_xfl[MROWS * 256];
__device__ uint32_t g_Wh[8][DMn * 256], g_Wl[8][DMn * 256];
__device__ uint32_t g_Qrh[Bn*Hn*Sn*32], g_Qrl[Bn*Hn*Sn*32];
__device__ uint32_t g_Krh[Bn*Hn*Sn*32], g_Krl[Bn*Hn*Sn*32];
__device__ uint32_t g_Qfh[Bn*Hn*Sn*32], g_Qfl[Bn*Hn*Sn*32];
__device__ uint32_t g_Kfh[Bn*Hn*Sn*32], g_Kfl[Bn*Hn*Sn*32];
__device__ uint32_t g_Vh[Bn*Hn*128*512], g_Vl[Bn*Hn*128*512];   // [bh][row: Vr d 0-63 | Vf d 64-127][s-pairs]
__device__ uint32_t g_Crh[MROWS * 256], g_Crl[MROWS * 256];
__device__ uint32_t g_Cfh[MROWS * 256], g_Cfl[MROWS * 256];
__device__ uint32_t g_Ph[(size_t)Bn*Hn*Sn*512], g_Pl[(size_t)Bn*Hn*Sn*512];
__device__ float g_Sr[(size_t)Bn * Hn * Sn * Sn];   // fp32 scores
__device__ float g_Sf[(size_t)Bn * Hn * Sn * Sn];

// ---------------- smem layout: two 32KB stages ----------------
#define T_AHI 0
#define T_ALO 8192
#define T_BHI 16384
#define T_BLO 24576
#define STAGE 32768
#define SMEM_BYTES 65536

__device__ __forceinline__ uint32_t smem_u32(const void* p) {
    uint32_t a;
    asm("{ .reg .u64 t; cvta.to.shared.u64 t, %1; cvt.u32.u64 %0, t; }" : "=r"(a) : "l"(p));
    return a;
}

#define CP_ASYNC16(dst, src) \
    asm volatile("cp.async.cg.shared.global [%0], [%1], 16;" :: "r"(dst), "l"(src))
#define CP_COMMIT() asm volatile("cp.async.commit_group;" ::: "memory")
#define CP_WAIT(n)  asm volatile("cp.async.wait_group %0;" :: "n"(n) : "memory")

__device__ __forceinline__ uint32_t bfpair(__nv_bfloat16 a, __nv_bfloat16 b) {
    __nv_bfloat162 t = __halves2bfloat162(a, b);
    return *reinterpret_cast<uint32_t*>(&t);
}

// store one (even k, k+1) fp32 pair into split hi/lo arrays at the permuted offset.
// rowbase32 = row * (K/2). Permutation matches the SMEM physical tile order:
// pair t (0..15) within a 32-k chunk -> group g, slot s.
__device__ __forceinline__ void split_pair_store(
    uint32_t* __restrict__ hi, uint32_t* __restrict__ lo,
    size_t rowbase32, int k, float v0, float v1)
{
    const int c = k >> 5, t = (k & 31) >> 1;
    const int g = ((t >> 3) << 1) | ((t >> 1) & 1);
    const int s = ((t & 1) << 1) | ((t >> 2) & 1);
    const size_t off = rowbase32 + c * 16 + g * 4 + s;
    __nv_bfloat16 h0 = __float2bfloat16_rn(v0), h1 = __float2bfloat16_rn(v1);
    hi[off] = bfpair(h0, h1);
    lo[off] = bfpair(__float2bfloat16_rn(v0 - __bfloat162float(h0)),
                     __float2bfloat16_rn(v1 - __bfloat162float(h1)));
}

// ---------------- generic fp32 -> split converter ----------------
__global__ void split_kernel(const float* __restrict__ X, uint32_t* __restrict__ hi,
                             uint32_t* __restrict__ lo, int K, size_t totalPairs)
{
    size_t i = (size_t)blockIdx.x * 256 + threadIdx.x;
    if (i >= totalPairs) return;
    const int ppr = K >> 1;
    size_t row = i / ppr;
    const int p = (int)(i - row * ppr);
    const int k = p * 2;
    float2 v = *reinterpret_cast<const float2*>(X + row * (size_t)K + k);
    split_pair_store(hi, lo, row * (size_t)ppr, k, v.x, v.y);
}

#define MMA(c, a, b) \
    asm volatile( \
        "mma.sync.aligned.m16n8k16.row.col.f32.bf16.bf16.f32 " \
        "{%0,%1,%2,%3},{%4,%5,%6,%7},{%8,%9},{%0,%1,%2,%3};" \
        : "+f"((c)[0]), "+f"((c)[1]), "+f"((c)[2]), "+f"((c)[3]) \
        : "r"((a)[0]), "r"((a)[1]), "r"((a)[2]), "r"((a)[3]), \
          "r"((b)[0]), "r"((b)[1]))

// ============ GEMM on pre-split operands. C = alpha*A*B^T (+bias) ============
// SMODE: 0 fp32 C0 (ldc=N), 1 split head-major Q/K (H0/L0), 2 split V-combined
//        transposed (H0/L0, vhalf selects rows 0-63 / 64-127), 3 PV split (H0/L0=Cr, H1/L1=Cf)
template <int SMODE>
__global__ void __launch_bounds__(256, 2) mma_gemm(
    const uint32_t* __restrict__ Ahi, const uint32_t* __restrict__ Alo,
    const uint32_t* __restrict__ Bhi, const uint32_t* __restrict__ Blo,
    const float* __restrict__ bias,
    float* __restrict__ C0,
    uint32_t* __restrict__ H0, uint32_t* __restrict__ L0,
    uint32_t* __restrict__ H1, uint32_t* __restrict__ L1,
    int N, int K, float alpha, int vhalf,
    long long strideA, long long strideB, long long strideC)
{
    extern __shared__ char smem[];
    const uint32_t sb = smem_u32(smem);
    const int tid = threadIdx.x;
    const int w = tid >> 5, lane = tid & 31;
    const int wm = w >> 2, wn = w & 3;
    const int g = lane >> 2, tig = lane & 3;
    const int bm = blockIdx.y * 128, bn = blockIdx.x * 128;
    const int z = blockIdx.z;
    const size_t aBase = (size_t)z * strideA;
    const size_t bBase = (size_t)z * strideB;
    if (SMODE == 0) C0 += (size_t)z * strideC;

    const int rowA32 = K >> 1;      // u32 per row

    float acc[4][4][4];
    #pragma unroll
    for (int i = 0; i < 4; i++)
        #pragma unroll
        for (int j = 0; j < 4; j++)
            #pragma unroll
            for (int c = 0; c < 4; c++) acc[i][j][c] = 0.f;

    // producer: pure 16B cp.async copies
    const int prr = tid >> 2, pg = tid & 3;
    const int nc = K >> 5;

    auto issue = [&](int cc, int st) {
        const uint32_t so = sb + st * STAGE;
        #pragma unroll
        for (int it = 0; it < 2; it++) {
            const int r = prr + it * 64;
            const uint32_t sw = (uint32_t)(r * 64 + ((pg * 16) ^ ((r & 2) << 4)));
            const size_t srcA = aBase + (size_t)(bm + r) * rowA32 + cc * 16 + pg * 4;
            const size_t srcB = bBase + (size_t)(bn + r) * rowA32 + cc * 16 + pg * 4;
            CP_ASYNC16(so + T_AHI + sw, Ahi + srcA);
            CP_ASYNC16(so + T_ALO + sw, Alo + srcA);
            CP_ASYNC16(so + T_BHI + sw, Bhi + srcB);
            CP_ASYNC16(so + T_BLO + sw, Blo + srcB);
        }
    };

    issue(0, 0);
    CP_COMMIT();

    for (int cc = 0; cc < nc; cc++) {
        if (cc + 1 < nc) { issue(cc + 1, (cc + 1) & 1); CP_COMMIT(); CP_WAIT(1); }
        else             { CP_WAIT(0); }
        __syncthreads();
        const char* sm = smem + (cc & 1) * STAGE;

        #pragma unroll
        for (int s = 0; s < 2; s++) {
            uint32_t bh[4][2], bl[4][2], Af[4][4];
            #pragma unroll
            for (int j = 0; j < 4; j++) {
                const int rB = wn * 32 + j * 8 + g;
                const uint32_t co = (uint32_t)((s * 32 + tig * 8) ^ ((rB & 2) << 4)) + rB * 64;
                uint2 u = *reinterpret_cast<const uint2*>(sm + T_BHI + co);
                bh[j][0] = u.x; bh[j][1] = u.y;
                uint2 v = *reinterpret_cast<const uint2*>(sm + T_BLO + co);
                bl[j][0] = v.x; bl[j][1] = v.y;
            }
            #pragma unroll
            for (int i = 0; i < 4; i++) {
                const int r0 = wm * 64 + i * 16 + g;
                const uint32_t co = (uint32_t)((s * 32 + tig * 8) ^ ((r0 & 2) << 4));
                uint2 u = *reinterpret_cast<const uint2*>(sm + T_AHI + r0 * 64 + co);
                uint2 v = *reinterpret_cast<const uint2*>(sm + T_AHI + (r0 + 8) * 64 + co);
                Af[i][0] = u.x; Af[i][1] = v.x; Af[i][2] = u.y; Af[i][3] = v.y;
            }
            #pragma unroll
            for (int i = 0; i < 4; i++)
                #pragma unroll
                for (int j = 0; j < 4; j++) MMA(acc[i][j], Af[i], bh[j]);
            #pragma unroll
            for (int i = 0; i < 4; i++)
                #pragma unroll
                for (int j = 0; j < 4; j++) MMA(acc[i][j], Af[i], bl[j]);
            #pragma unroll
            for (int i = 0; i < 4; i++) {
                const int r0 = wm * 64 + i * 16 + g;
                const uint32_t co = (uint32_t)((s * 32 + tig * 8) ^ ((r0 & 2) << 4));
                uint2 u = *reinterpret_cast<const uint2*>(sm + T_ALO + r0 * 64 + co);
                uint2 v = *reinterpret_cast<const uint2*>(sm + T_ALO + (r0 + 8) * 64 + co);
                Af[i][0] = u.x; Af[i][1] = v.x; Af[i][2] = u.y; Af[i][3] = v.y;
            }
            #pragma unroll
            for (int i = 0; i < 4; i++)
                #pragma unroll
                for (int j = 0; j < 4; j++) MMA(acc[i][j], Af[i], bh[j]);
        }
        __syncthreads();
    }

    // ---- epilogue: two 64-row halves through smem stage (stage 0 area) ----
    float* sC = reinterpret_cast<float*>(smem);
    #pragma unroll
    for (int hh = 0; hh < 2; hh++) {
        if (wm == hh) {
            #pragma unroll
            for (int i = 0; i < 4; i++) {
                const int rl = i * 16 + g;
                #pragma unroll
                for (int j = 0; j < 4; j++) {
                    const int cl = wn * 32 + j * 8 + 2 * tig;
                    float bv0 = 0.f, bv1 = 0.f;
                    if (bias) { bv0 = __ldg(bias + bn + cl); bv1 = __ldg(bias + bn + cl + 1); }
                    float2 v0 = make_float2(acc[i][j][0] * alpha + bv0,
                                            acc[i][j][1] * alpha + bv1);
                    float2 v1 = make_float2(acc[i][j][2] * alpha + bv0,
                                            acc[i][j][3] * alpha + bv1);
                    *reinterpret_cast<float2*>(&sC[rl * 132 + cl]) = v0;
                    *reinterpret_cast<float2*>(&sC[(rl + 8) * 132 + cl]) = v1;
                }
            }
        }
        __syncthreads();

        const int mbase = bm + hh * 64;
        if (SMODE == 0) {
            for (int e = tid * 4; e < 64 * 128; e += 1024) {
                const int row = e >> 7, col = e & 127;
                float4 v = make_float4(sC[row * 132 + col],     sC[row * 132 + col + 1],
                                       sC[row * 132 + col + 2], sC[row * 132 + col + 3]);
                *reinterpret_cast<float4*>(&C0[(size_t)(mbase + row) * N + bn + col]) = v;
            }
        } else if (SMODE == 1) {
            const int b = mbase >> 10, s0 = mbase & 1023, h0 = bn >> 6;
            for (int e = tid; e < 64 * 64; e += 256) {
                const int rl = e >> 6, p = e & 63, col = p * 2;
                const int hd = col >> 6, d = col & 63;
                const size_t rowIdx = ((size_t)(b * Hn + h0 + hd)) * Sn + s0 + rl;
                split_pair_store(H0, L0, rowIdx * 32, d,
                                 sC[rl * 132 + col], sC[rl * 132 + col + 1]);
            }
        } else if (SMODE == 2) {
            const int b = mbase >> 10, sLoc = mbase & 1023, h0 = bn >> 6;
            for (int e = tid; e < 32 * 128; e += 256) {
                const int col = e & 127, sl = (e >> 7) * 2;
                const int hd = col >> 6, d = col & 63;
                const size_t vrow = ((size_t)(b * Hn + h0 + hd)) * 128 + vhalf * 64 + d;
                split_pair_store(H0, L0, vrow * 512, sLoc + sl,
                                 sC[sl * 132 + col], sC[(sl + 1) * 132 + col]);
            }
        } else {  // SMODE == 3
            const int b = z >> 3, h = z & 7;
            for (int e = tid; e < 64 * 64; e += 256) {
                const int rl = e >> 6, p = e & 63;
                const int str = p >> 5, d = (p & 31) * 2;
                const int col = str * 64 + d;
                const size_t rowIdx = (size_t)b * Sn + mbase + rl;
                uint32_t* H = str ? H1 : H0;
                uint32_t* L = str ? L1 : L0;
                split_pair_store(H, L, rowIdx * 256, h * 64 + d,
                                 sC[rl * 132 + col], sC[rl * 132 + col + 1]);
            }
        }
        __syncthreads();
    }
}

// ---------------- fast exp ----------------
__device__ __forceinline__ float fexp(float x) {
    float t  = x * 1.4426950408889634f;
    float fi = rintf(t);
    float f  = t - fi;
    float p  = 1.3333558146428443e-3f;
    p = fmaf(p, f, 9.6181291076284770e-3f);
    p = fmaf(p, f, 5.5504108664821580e-2f);
    p = fmaf(p, f, 2.4022650695910072e-1f);
    p = fmaf(p, f, 6.9314718055994531e-1f);
    p = fmaf(p, f, 1.0f);
    int e = (int)fi;
    return __int_as_float(__float_as_int(p) + (e << 23));
}

// ---------------- softmax + max merge -> split P ----------------
__global__ void __launch_bounds__(256) softmax_max_kernel(
    const float* __restrict__ Sr, const float* __restrict__ Sf,
    uint32_t* __restrict__ Phi, uint32_t* __restrict__ Plo)
{
    __shared__ float sred[8];
    const size_t row = blockIdx.x;
    const int t = threadIdx.x;

    float4 xr = reinterpret_cast<const float4*>(Sr + row * Sn)[t];
    float4 xf = reinterpret_cast<const float4*>(Sf + row * Sn)[t];

    float m = fmaxf(fmaxf(xr.x, xr.y), fmaxf(xr.z, xr.w));
    #pragma unroll
    for (int o = 16; o; o >>= 1) m = fmaxf(m, __shfl_xor_sync(0xffffffffu, m, o));
    if ((t & 31) == 0) sred[t >> 5] = m;
    __syncthreads();
    m = sred[0];
    #pragma unroll
    for (int i = 1; i < 8; i++) m = fmaxf(m, sred[i]);

    float er0 = fexp(xr.x - m), er1 = fexp(xr.y - m);
    float er2 = fexp(xr.z - m), er3 = fexp(xr.w - m);
    float s = er0 + er1 + er2 + er3;
    #pragma unroll
    for (int o = 16; o; o >>= 1) s += __shfl_xor_sync(0xffffffffu, s, o);
    __syncthreads();
    if ((t & 31) == 0) sred[t >> 5] = s;
    __syncthreads();
    s = sred[0];
    #pragma unroll
    for (int i = 1; i < 8; i++) s += sred[i];
    const float invZr = 1.0f / s;

    float mf = fmaxf(fmaxf(xf.x, xf.y), fmaxf(xf.z, xf.w));
    #pragma unroll
    for (int o = 16; o; o >>= 1) mf = fmaxf(mf, __shfl_xor_sync(0xffffffffu, mf, o));
    __syncthreads();
    if ((t & 31) == 0) sred[t >> 5] = mf;
    __syncthreads();
    mf = sred[0];
    #pragma unroll
    for (int i = 1; i < 8; i++) mf = fmaxf(mf, sred[i]);

    float ef0 = fexp(xf.x - mf), ef1 = fexp(xf.y - mf);
    float ef2 = fexp(xf.z - mf), ef3 = fexp(xf.w - mf);
    float sf = ef0 + ef1 + ef2 + ef3;
    #pragma unroll
    for (int o = 16; o; o >>= 1) sf += __shfl_xor_sync(0xffffffffu, sf, o);
    __syncthreads();
    if ((t & 31) == 0) sred[t >> 5] = sf;
    __syncthreads();
    sf = sred[0];
    #pragma unroll
    for (int i = 1; i < 8; i++) sf += sred[i];
    const float invZf = 1.0f / sf;

    float4 p;
    p.x = fmaxf(er0 * invZr, ef0 * invZf);
    p.y = fmaxf(er1 * invZr, ef1 * invZf);
    p.z = fmaxf(er2 * invZr, ef2 * invZf);
    p.w = fmaxf(er3 * invZr, ef3 * invZf);

    const size_t rb = row * 512;
    split_pair_store(Phi, Plo, rb, 4 * t,     p.x, p.y);
    split_pair_store(Phi, Plo, rb, 4 * t + 2, p.z, p.w);
}

// ---------------- host ----------------
extern "C" void kernel_launch(void* const* d_in, const int* in_sizes, int n_in,
                              void* d_out, int out_size)
{
    const float* x_rgb  = (const float*)d_in[0];
    const float* x_flow = (const float*)d_in[1];
    const float* W[8]; const float* bW[8];
    for (int i = 0; i < 8; i++) { W[i] = (const float*)d_in[2 + 2*i]; bW[i] = (const float*)d_in[3 + 2*i]; }
    // order: Wq1 bq1 Wk1 bk1 Wv1 bv1 Wq2 bq2 Wk2 bk2 Wv2 bv2 Wo1 bo1 Wo2 bo2
    float* out = (float*)d_out;

    uint32_t *xrh,*xrl,*xfh,*xfl,*Wh,*Wl;
    uint32_t *Qrh,*Qrl,*Krh,*Krl,*Qfh,*Qfl,*Kfh,*Kfl,*Vh,*Vl,*Crh,*Crl,*Cfh,*Cfl,*Ph,*Pl;
    float *Sr,*Sf;
    cudaGetSymbolAddress((void**)&xrh, g_xrh); cudaGetSymbolAddress((void**)&xrl, g_xrl);
    cudaGetSymbolAddress((void**)&xfh, g_xfh); cudaGetSymbolAddress((void**)&xfl, g_xfl);
    cudaGetSymbolAddress((void**)&Wh, g_Wh);   cudaGetSymbolAddress((void**)&Wl, g_Wl);
    cudaGetSymbolAddress((void**)&Qrh, g_Qrh); cudaGetSymbolAddress((void**)&Qrl, g_Qrl);
    cudaGetSymbolAddress((void**)&Krh, g_Krh); cudaGetSymbolAddress((void**)&Krl, g_Krl);
    cudaGetSymbolAddress((void**)&Qfh, g_Qfh); cudaGetSymbolAddress((void**)&Qfl, g_Qfl);
    cudaGetSymbolAddress((void**)&Kfh, g_Kfh); cudaGetSymbolAddress((void**)&Kfl, g_Kfl);
    cudaGetSymbolAddress((void**)&Vh, g_Vh);   cudaGetSymbolAddress((void**)&Vl, g_Vl);
    cudaGetSymbolAddress((void**)&Crh, g_Crh); cudaGetSymbolAddress((void**)&Crl, g_Crl);
    cudaGetSymbolAddress((void**)&Cfh, g_Cfh); cudaGetSymbolAddress((void**)&Cfl, g_Cfl);
    cudaGetSymbolAddress((void**)&Ph, g_Ph);   cudaGetSymbolAddress((void**)&Pl, g_Pl);
    cudaGetSymbolAddress((void**)&Sr, g_Sr);   cudaGetSymbolAddress((void**)&Sf, g_Sf);

    cudaFuncSetAttribute((const void*)mma_gemm<0>, cudaFuncAttributeMaxDynamicSharedMemorySize, SMEM_BYTES);
    cudaFuncSetAttribute((const void*)mma_gemm<1>, cudaFuncAttributeMaxDynamicSharedMemorySize, SMEM_BYTES);
    cudaFuncSetAttribute((const void*)mma_gemm<2>, cudaFuncAttributeMaxDynamicSharedMemorySize, SMEM_BYTES);
    cudaFuncSetAttribute((const void*)mma_gemm<3>, cudaFuncAttributeMaxDynamicSharedMemorySize, SMEM_BYTES);

    const dim3 blk(256);

    // 0) pre-split inputs + weights
    split_kernel<<<MROWS, 256>>>(x_rgb,  xrh, xrl, DMn, (size_t)MROWS * 256);
    split_kernel<<<MROWS, 256>>>(x_flow, xfh, xfl, DMn, (size_t)MROWS * 256);
    for (int i = 0; i < 8; i++)
        split_kernel<<<DMn / 2 * 2, 256>>>(W[i], Wh + (size_t)i * DMn * 256,
                                           Wl + (size_t)i * DMn * 256, DMn, (size_t)DMn * 256);

    // 1) projections
    const dim3 gP(DMn / 128, MROWS / 128, 1);
    #define WH(i) (Wh + (size_t)(i) * DMn * 256)
    #define WL(i) (Wl + (size_t)(i) * DMn * 256)
    mma_gemm<1><<<gP, blk, SMEM_BYTES>>>(xrh, xrl, WH(0), WL(0), bW[0], nullptr,
                                         Qrh, Qrl, nullptr, nullptr, DMn, DMn, 1.f, 0, 0, 0, 0);
    mma_gemm<1><<<gP, blk, SMEM_BYTES>>>(xrh, xrl, WH(1), WL(1), bW[1], nullptr,
                                         Krh, Krl, nullptr, nullptr, DMn, DMn, 1.f, 0, 0, 0, 0);
    mma_gemm<2><<<gP, blk, SMEM_BYTES>>>(xrh, xrl, WH(2), WL(2), bW[2], nullptr,
                                         Vh, Vl, nullptr, nullptr, DMn, DMn, 1.f, 0, 0, 0, 0);
    mma_gemm<1><<<gP, blk, SMEM_BYTES>>>(xfh, xfl, WH(3), WL(3), bW[3], nullptr,
                                         Qfh, Qfl, nullptr, nullptr, DMn, DMn, 1.f, 0, 0, 0, 0);
    mma_gemm<1><<<gP, blk, SMEM_BYTES>>>(xfh, xfl, WH(4), WL(4), bW[4], nullptr,
                                         Kfh, Kfl, nullptr, nullptr, DMn, DMn, 1.f, 0, 0, 0, 0);
    mma_gemm<2><<<gP, blk, SMEM_BYTES>>>(xfh, xfl, WH(5), WL(5), bW[5], nullptr,
                                         Vh, Vl, nullptr, nullptr, DMn, DMn, 1.f, 1, 0, 0, 0);

    // 2) scores (batched over b*h)
    const dim3 gS(Sn / 128, Sn / 128, Bn * Hn);
    mma_gemm<0><<<gS, blk, SMEM_BYTES>>>(Qrh, Qrl, Krh, Krl, nullptr, Sr,
                                         nullptr, nullptr, nullptr, nullptr,
                                         Sn, DKn, 0.125f, 0,
                                         Sn * 32, Sn * 32, (long long)Sn * Sn);
    mma_gemm<0><<<gS, blk, SMEM_BYTES>>>(Qfh, Qfl, Kfh, Kfl, nullptr, Sf,
                                         nullptr, nullptr, nullptr, nullptr,
                                         Sn, DKn, 0.125f, 0,
                                         Sn * 32, Sn * 32, (long long)Sn * Sn);

    // 3) softmax + max merge -> split P
    softmax_max_kernel<<<Bn * Hn * Sn, 256>>>(Sr, Sf, Ph, Pl);

    // 4) PV for both streams (combined V panel)
    mma_gemm<3><<<dim3(1, Sn / 128, Bn * Hn), blk, SMEM_BYTES>>>(
        Ph, Pl, Vh, Vl, nullptr, nullptr, Crh, Crl, Cfh, Cfl,
        128, Sn, 1.f, 0,
        (long long)Sn * 512, (long long)128 * 512, 0);

    // 5) output projections
    const dim3 gO(DMn / 128, MROWS / 128, 1);
    mma_gemm<0><<<gO, blk, SMEM_BYTES>>>(Crh, Crl, WH(6), WL(6), bW[6], out,
                                         nullptr, nullptr, nullptr, nullptr,
                                         DMn, DMn, 1.f, 0, 0, 0, 0);
    mma_gemm<0><<<gO, blk, SMEM_BYTES>>>(Cfh, Cfl, WH(7), WL(7), bW[7],
                                         out + (size_t)MROWS * DMn,
                                         nullptr, nullptr, nullptr, nullptr,
                                         DMn, DMn, 1.f, 0, 0, 0, 0);
}

// round 7
// speedup vs baseline: 3.1560x; 1.3021x over previous
#include <cuda_runtime.h>
#include <cuda_fp16.h>
#include <stdint.h>
#include <math.h>

#define Bn 8
#define Hn 8
#define Sn 1024
#define DMn 512
#define DKn 64
#define MROWS (Bn * Sn)   // 8192

// ---------------- scratch (device globals; no runtime allocation) ----------------
// operands stored as uint32 (2 fp16) in per-32k-chunk interleaved order.
// A-side operands: split hi/lo. B-side operands: single fp16.
__device__ uint32_t g_xrh[MROWS * 256], g_xrl[MROWS * 256];
__device__ uint32_t g_xfh[MROWS * 256], g_xfl[MROWS * 256];
__device__ uint32_t g_W[8][DMn * 256];                         // single fp16 weights
__device__ uint32_t g_Qrh[Bn*Hn*Sn*32], g_Qrl[Bn*Hn*Sn*32];
__device__ uint32_t g_Qfh[Bn*Hn*Sn*32], g_Qfl[Bn*Hn*Sn*32];
__device__ uint32_t g_Kr[Bn*Hn*Sn*32];                         // single fp16 K
__device__ uint32_t g_Kf[Bn*Hn*Sn*32];
__device__ uint32_t g_V[Bn*Hn*128*512];                        // single fp16, [bh][Vr d0-63|Vf d64-127][s-pairs]
__device__ uint32_t g_Crh[MROWS * 256], g_Crl[MROWS * 256];
__device__ uint32_t g_Cfh[MROWS * 256], g_Cfl[MROWS * 256];
__device__ uint32_t g_Ph[(size_t)Bn*Hn*Sn*512], g_Pl[(size_t)Bn*Hn*Sn*512];
__device__ float g_Sr[(size_t)Bn * Hn * Sn * Sn];              // fp32 scores
__device__ float g_Sf[(size_t)Bn * Hn * Sn * Sn];

// ---------------- smem layout: two 24KB stages ----------------
#define T_AHI 0
#define T_ALO 8192
#define T_B   16384
#define STAGE 24576
#define SMEM_BYTES 49152

__device__ __forceinline__ uint32_t smem_u32(const void* p) {
    uint32_t a;
    asm("{ .reg .u64 t; cvta.to.shared.u64 t, %1; cvt.u32.u64 %0, t; }" : "=r"(a) : "l"(p));
    return a;
}

#define CP_ASYNC16(dst, src) \
    asm volatile("cp.async.cg.shared.global [%0], [%1], 16;" :: "r"(dst), "l"(src))
#define CP_COMMIT() asm volatile("cp.async.commit_group;" ::: "memory")
#define CP_WAIT(n)  asm volatile("cp.async.wait_group %0;" :: "n"(n) : "memory")

__device__ __forceinline__ uint32_t hpair(__half a, __half b) {
    __half2 t = __halves2half2(a, b);
    return *reinterpret_cast<uint32_t*>(&t);
}

// permuted offset within a row for k (even), matching SMEM physical tile order
__device__ __forceinline__ size_t perm_off(size_t rowbase32, int k) {
    const int c = k >> 5, t = (k & 31) >> 1;
    const int g = ((t >> 3) << 1) | ((t >> 1) & 1);
    const int s = ((t & 1) << 1) | ((t >> 2) & 1);
    return rowbase32 + c * 16 + g * 4 + s;
}

// split fp32 pair -> fp16 hi/lo arrays at permuted offset
__device__ __forceinline__ void split_pair_store(
    uint32_t* __restrict__ hi, uint32_t* __restrict__ lo,
    size_t rowbase32, int k, float v0, float v1)
{
    const size_t off = perm_off(rowbase32, k);
    __half h0 = __float2half_rn(v0), h1 = __float2half_rn(v1);
    hi[off] = hpair(h0, h1);
    lo[off] = hpair(__float2half_rn(v0 - __half2float(h0)),
                    __float2half_rn(v1 - __half2float(h1)));
}

// single fp16 store at permuted offset
__device__ __forceinline__ void single_pair_store(
    uint32_t* __restrict__ dst, size_t rowbase32, int k, float v0, float v1)
{
    dst[perm_off(rowbase32, k)] = hpair(__float2half_rn(v0), __float2half_rn(v1));
}

// ---------------- fp32 -> split / single converters ----------------
__global__ void split_kernel(const float* __restrict__ X, uint32_t* __restrict__ hi,
                             uint32_t* __restrict__ lo, int K, size_t totalPairs)
{
    size_t i = (size_t)blockIdx.x * 256 + threadIdx.x;
    if (i >= totalPairs) return;
    const int ppr = K >> 1;
    size_t row = i / ppr;
    const int k = (int)(i - row * ppr) * 2;
    float2 v = *reinterpret_cast<const float2*>(X + row * (size_t)K + k);
    split_pair_store(hi, lo, row * (size_t)ppr, k, v.x, v.y);
}

__global__ void split1_kernel(const float* __restrict__ X, uint32_t* __restrict__ dst,
                              int K, size_t totalPairs)
{
    size_t i = (size_t)blockIdx.x * 256 + threadIdx.x;
    if (i >= totalPairs) return;
    const int ppr = K >> 1;
    size_t row = i / ppr;
    const int k = (int)(i - row * ppr) * 2;
    float2 v = *reinterpret_cast<const float2*>(X + row * (size_t)K + k);
    single_pair_store(dst, row * (size_t)ppr, k, v.x, v.y);
}

#define MMA(c, a, b) \
    asm volatile( \
        "mma.sync.aligned.m16n8k16.row.col.f32.f16.f16.f32 " \
        "{%0,%1,%2,%3},{%4,%5,%6,%7},{%8,%9},{%0,%1,%2,%3};" \
        : "+f"((c)[0]), "+f"((c)[1]), "+f"((c)[2]), "+f"((c)[3]) \
        : "r"((a)[0]), "r"((a)[1]), "r"((a)[2]), "r"((a)[3]), \
          "r"((b)[0]), "r"((b)[1]))

// ============ GEMM: C = alpha*(Ah+Al)*B^T (+bias). A split fp16, B single fp16 ============
// SMODE: 0 fp32 C0 (ldc=N), 1 split head-major (Q), 2 single V-combined transposed
//        (vhalf selects rows 0-63/64-127), 3 PV split (H0/L0=Cr, H1/L1=Cf),
//        4 single head-major (K)
template <int SMODE>
__global__ void __launch_bounds__(256, 2) mma_gemm(
    const uint32_t* __restrict__ Ahi, const uint32_t* __restrict__ Alo,
    const uint32_t* __restrict__ Bs,
    const float* __restrict__ bias,
    float* __restrict__ C0,
    uint32_t* __restrict__ H0, uint32_t* __restrict__ L0,
    uint32_t* __restrict__ H1, uint32_t* __restrict__ L1,
    int N, int K, float alpha, int vhalf,
    long long strideA, long long strideB, long long strideC)
{
    extern __shared__ char smem[];
    const uint32_t sb = smem_u32(smem);
    const int tid = threadIdx.x;
    const int w = tid >> 5, lane = tid & 31;
    const int wm = w >> 2, wn = w & 3;
    const int g = lane >> 2, tig = lane & 3;
    const int bm = blockIdx.y * 128, bn = blockIdx.x * 128;
    const int z = blockIdx.z;
    const size_t aBase = (size_t)z * strideA;
    const size_t bBase = (size_t)z * strideB;
    if (SMODE == 0) C0 += (size_t)z * strideC;

    const int rowA32 = K >> 1;      // u32 per row

    float acc[4][4][4];
    #pragma unroll
    for (int i = 0; i < 4; i++)
        #pragma unroll
        for (int j = 0; j < 4; j++)
            #pragma unroll
            for (int c = 0; c < 4; c++) acc[i][j][c] = 0.f;

    const int prr = tid >> 2, pg = tid & 3;
    const int nc = K >> 5;

    auto issue = [&](int cc, int st) {
        const uint32_t so = sb + st * STAGE;
        #pragma unroll
        for (int it = 0; it < 2; it++) {
            const int r = prr + it * 64;
            const uint32_t sw = (uint32_t)(r * 64 + ((pg * 16) ^ ((r & 2) << 4)));
            const size_t srcA = aBase + (size_t)(bm + r) * rowA32 + cc * 16 + pg * 4;
            const size_t srcB = bBase + (size_t)(bn + r) * rowA32 + cc * 16 + pg * 4;
            CP_ASYNC16(so + T_AHI + sw, Ahi + srcA);
            CP_ASYNC16(so + T_ALO + sw, Alo + srcA);
            CP_ASYNC16(so + T_B   + sw, Bs  + srcB);
        }
    };

    issue(0, 0);
    CP_COMMIT();

    for (int cc = 0; cc < nc; cc++) {
        if (cc + 1 < nc) { issue(cc + 1, (cc + 1) & 1); CP_COMMIT(); CP_WAIT(1); }
        else             { CP_WAIT(0); }
        __syncthreads();
        const char* sm = smem + (cc & 1) * STAGE;

        #pragma unroll
        for (int s = 0; s < 2; s++) {
            uint32_t bfr[4][2], Af[4][4];
            #pragma unroll
            for (int j = 0; j < 4; j++) {
                const int rB = wn * 32 + j * 8 + g;
                const uint32_t co = (uint32_t)((s * 32 + tig * 8) ^ ((rB & 2) << 4)) + rB * 64;
                uint2 u = *reinterpret_cast<const uint2*>(sm + T_B + co);
                bfr[j][0] = u.x; bfr[j][1] = u.y;
            }
            #pragma unroll
            for (int i = 0; i < 4; i++) {
                const int r0 = wm * 64 + i * 16 + g;
                const uint32_t co = (uint32_t)((s * 32 + tig * 8) ^ ((r0 & 2) << 4));
                uint2 u = *reinterpret_cast<const uint2*>(sm + T_AHI + r0 * 64 + co);
                uint2 v = *reinterpret_cast<const uint2*>(sm + T_AHI + (r0 + 8) * 64 + co);
                Af[i][0] = u.x; Af[i][1] = v.x; Af[i][2] = u.y; Af[i][3] = v.y;
            }
            #pragma unroll
            for (int i = 0; i < 4; i++)
                #pragma unroll
                for (int j = 0; j < 4; j++) MMA(acc[i][j], Af[i], bfr[j]);
            #pragma unroll
            for (int i = 0; i < 4; i++) {
                const int r0 = wm * 64 + i * 16 + g;
                const uint32_t co = (uint32_t)((s * 32 + tig * 8) ^ ((r0 & 2) << 4));
                uint2 u = *reinterpret_cast<const uint2*>(sm + T_ALO + r0 * 64 + co);
                uint2 v = *reinterpret_cast<const uint2*>(sm + T_ALO + (r0 + 8) * 64 + co);
                Af[i][0] = u.x; Af[i][1] = v.x; Af[i][2] = u.y; Af[i][3] = v.y;
            }
            #pragma unroll
            for (int i = 0; i < 4; i++)
                #pragma unroll
                for (int j = 0; j < 4; j++) MMA(acc[i][j], Af[i], bfr[j]);
        }
        __syncthreads();
    }

    // ---- epilogue: two 64-row halves through smem stage ----
    float* sC = reinterpret_cast<float*>(smem);
    #pragma unroll
    for (int hh = 0; hh < 2; hh++) {
        if (wm == hh) {
            #pragma unroll
            for (int i = 0; i < 4; i++) {
                const int rl = i * 16 + g;
                #pragma unroll
                for (int j = 0; j < 4; j++) {
                    const int cl = wn * 32 + j * 8 + 2 * tig;
                    float bv0 = 0.f, bv1 = 0.f;
                    if (bias) { bv0 = __ldg(bias + bn + cl); bv1 = __ldg(bias + bn + cl + 1); }
                    float2 v0 = make_float2(acc[i][j][0] * alpha + bv0,
                                            acc[i][j][1] * alpha + bv1);
                    float2 v1 = make_float2(acc[i][j][2] * alpha + bv0,
                                            acc[i][j][3] * alpha + bv1);
                    *reinterpret_cast<float2*>(&sC[rl * 132 + cl]) = v0;
                    *reinterpret_cast<float2*>(&sC[(rl + 8) * 132 + cl]) = v1;
                }
            }
        }
        __syncthreads();

        const int mbase = bm + hh * 64;
        if (SMODE == 0) {
            for (int e = tid * 4; e < 64 * 128; e += 1024) {
                const int row = e >> 7, col = e & 127;
                float4 v = make_float4(sC[row * 132 + col],     sC[row * 132 + col + 1],
                                       sC[row * 132 + col + 2], sC[row * 132 + col + 3]);
                *reinterpret_cast<float4*>(&C0[(size_t)(mbase + row) * N + bn + col]) = v;
            }
        } else if (SMODE == 1 || SMODE == 4) {
            const int b = mbase >> 10, s0 = mbase & 1023, h0 = bn >> 6;
            for (int e = tid; e < 64 * 64; e += 256) {
                const int rl = e >> 6, p = e & 63, col = p * 2;
                const int hd = col >> 6, d = col & 63;
                const size_t rowIdx = ((size_t)(b * Hn + h0 + hd)) * Sn + s0 + rl;
                if (SMODE == 1)
                    split_pair_store(H0, L0, rowIdx * 32, d,
                                     sC[rl * 132 + col], sC[rl * 132 + col + 1]);
                else
                    single_pair_store(H0, rowIdx * 32, d,
                                      sC[rl * 132 + col], sC[rl * 132 + col + 1]);
            }
        } else if (SMODE == 2) {
            const int b = mbase >> 10, sLoc = mbase & 1023, h0 = bn >> 6;
            for (int e = tid; e < 32 * 128; e += 256) {
                const int col = e & 127, sl = (e >> 7) * 2;
                const int hd = col >> 6, d = col & 63;
                const size_t vrow = ((size_t)(b * Hn + h0 + hd)) * 128 + vhalf * 64 + d;
                single_pair_store(H0, vrow * 512, sLoc + sl,
                                  sC[sl * 132 + col], sC[(sl + 1) * 132 + col]);
            }
        } else {  // SMODE == 3
            const int b = z >> 3, h = z & 7;
            for (int e = tid; e < 64 * 64; e += 256) {
                const int rl = e >> 6, p = e & 63;
                const int str = p >> 5, d = (p & 31) * 2;
                const int col = str * 64 + d;
                const size_t rowIdx = (size_t)b * Sn + mbase + rl;
                uint32_t* H = str ? H1 : H0;
                uint32_t* L = str ? L1 : L0;
                split_pair_store(H, L, rowIdx * 256, h * 64 + d,
                                 sC[rl * 132 + col], sC[rl * 132 + col + 1]);
            }
        }
        __syncthreads();
    }
}

// ---------------- fast exp ----------------
__device__ __forceinline__ float fexp(float x) {
    float t  = x * 1.4426950408889634f;
    float fi = rintf(t);
    float f  = t - fi;
    float p  = 1.3333558146428443e-3f;
    p = fmaf(p, f, 9.6181291076284770e-3f);
    p = fmaf(p, f, 5.5504108664821580e-2f);
    p = fmaf(p, f, 2.4022650695910072e-1f);
    p = fmaf(p, f, 6.9314718055994531e-1f);
    p = fmaf(p, f, 1.0f);
    int e = (int)fi;
    return __int_as_float(__float_as_int(p) + (e << 23));
}

// ---------------- softmax + max merge -> split fp16 P ----------------
__global__ void __launch_bounds__(256) softmax_max_kernel(
    const float* __restrict__ Sr, const float* __restrict__ Sf,
    uint32_t* __restrict__ Phi, uint32_t* __restrict__ Plo)
{
    __shared__ float sred[8];
    const size_t row = blockIdx.x;
    const int t = threadIdx.x;

    float4 xr = reinterpret_cast<const float4*>(Sr + row * Sn)[t];
    float4 xf = reinterpret_cast<const float4*>(Sf + row * Sn)[t];

    float m = fmaxf(fmaxf(xr.x, xr.y), fmaxf(xr.z, xr.w));
    #pragma unroll
    for (int o = 16; o; o >>= 1) m = fmaxf(m, __shfl_xor_sync(0xffffffffu, m, o));
    if ((t & 31) == 0) sred[t >> 5] = m;
    __syncthreads();
    m = sred[0];
    #pragma unroll
    for (int i = 1; i < 8; i++) m = fmaxf(m, sred[i]);

    float er0 = fexp(xr.x - m), er1 = fexp(xr.y - m);
    float er2 = fexp(xr.z - m), er3 = fexp(xr.w - m);
    float s = er0 + er1 + er2 + er3;
    #pragma unroll
    for (int o = 16; o; o >>= 1) s += __shfl_xor_sync(0xffffffffu, s, o);
    __syncthreads();
    if ((t & 31) == 0) sred[t >> 5] = s;
    __syncthreads();
    s = sred[0];
    #pragma unroll
    for (int i = 1; i < 8; i++) s += sred[i];
    const float invZr = 1.0f / s;

    float mf = fmaxf(fmaxf(xf.x, xf.y), fmaxf(xf.z, xf.w));
    #pragma unroll
    for (int o = 16; o; o >>= 1) mf = fmaxf(mf, __shfl_xor_sync(0xffffffffu, mf, o));
    __syncthreads();
    if ((t & 31) == 0) sred[t >> 5] = mf;
    __syncthreads();
    mf = sred[0];
    #pragma unroll
    for (int i = 1; i < 8; i++) mf = fmaxf(mf, sred[i]);

    float ef0 = fexp(xf.x - mf), ef1 = fexp(xf.y - mf);
    float ef2 = fexp(xf.z - mf), ef3 = fexp(xf.w - mf);
    float sf = ef0 + ef1 + ef2 + ef3;
    #pragma unroll
    for (int o = 16; o; o >>= 1) sf += __shfl_xor_sync(0xffffffffu, sf, o);
    __syncthreads();
    if ((t & 31) == 0) sred[t >> 5] = sf;
    __syncthreads();
    sf = sred[0];
    #pragma unroll
    for (int i = 1; i < 8; i++) sf += sred[i];
    const float invZf = 1.0f / sf;

    float4 p;
    p.x = fmaxf(er0 * invZr, ef0 * invZf);
    p.y = fmaxf(er1 * invZr, ef1 * invZf);
    p.z = fmaxf(er2 * invZr, ef2 * invZf);
    p.w = fmaxf(er3 * invZr, ef3 * invZf);

    const size_t rb = row * 512;
    split_pair_store(Phi, Plo, rb, 4 * t,     p.x, p.y);
    split_pair_store(Phi, Plo, rb, 4 * t + 2, p.z, p.w);
}

// ---------------- host ----------------
extern "C" void kernel_launch(void* const* d_in, const int* in_sizes, int n_in,
                              void* d_out, int out_size)
{
    const float* x_rgb  = (const float*)d_in[0];
    const float* x_flow = (const float*)d_in[1];
    const float* W[8]; const float* bW[8];
    for (int i = 0; i < 8; i++) { W[i] = (const float*)d_in[2 + 2*i]; bW[i] = (const float*)d_in[3 + 2*i]; }
    // order: Wq1 bq1 Wk1 bk1 Wv1 bv1 Wq2 bq2 Wk2 bk2 Wv2 bv2 Wo1 bo1 Wo2 bo2
    float* out = (float*)d_out;

    uint32_t *xrh,*xrl,*xfh,*xfl,*Wd;
    uint32_t *Qrh,*Qrl,*Qfh,*Qfl,*Kr,*Kf,*V,*Crh,*Crl,*Cfh,*Cfl,*Ph,*Pl;
    float *Sr,*Sf;
    cudaGetSymbolAddress((void**)&xrh, g_xrh); cudaGetSymbolAddress((void**)&xrl, g_xrl);
    cudaGetSymbolAddress((void**)&xfh, g_xfh); cudaGetSymbolAddress((void**)&xfl, g_xfl);
    cudaGetSymbolAddress((void**)&Wd, g_W);
    cudaGetSymbolAddress((void**)&Qrh, g_Qrh); cudaGetSymbolAddress((void**)&Qrl, g_Qrl);
    cudaGetSymbolAddress((void**)&Qfh, g_Qfh); cudaGetSymbolAddress((void**)&Qfl, g_Qfl);
    cudaGetSymbolAddress((void**)&Kr, g_Kr);   cudaGetSymbolAddress((void**)&Kf, g_Kf);
    cudaGetSymbolAddress((void**)&V, g_V);
    cudaGetSymbolAddress((void**)&Crh, g_Crh); cudaGetSymbolAddress((void**)&Crl, g_Crl);
    cudaGetSymbolAddress((void**)&Cfh, g_Cfh); cudaGetSymbolAddress((void**)&Cfl, g_Cfl);
    cudaGetSymbolAddress((void**)&Ph, g_Ph);   cudaGetSymbolAddress((void**)&Pl, g_Pl);
    cudaGetSymbolAddress((void**)&Sr, g_Sr);   cudaGetSymbolAddress((void**)&Sf, g_Sf);

    cudaFuncSetAttribute((const void*)mma_gemm<0>, cudaFuncAttributeMaxDynamicSharedMemorySize, SMEM_BYTES);
    cudaFuncSetAttribute((const void*)mma_gemm<1>, cudaFuncAttributeMaxDynamicSharedMemorySize, SMEM_BYTES);
    cudaFuncSetAttribute((const void*)mma_gemm<2>, cudaFuncAttributeMaxDynamicSharedMemorySize, SMEM_BYTES);
    cudaFuncSetAttribute((const void*)mma_gemm<3>, cudaFuncAttributeMaxDynamicSharedMemorySize, SMEM_BYTES);
    cudaFuncSetAttribute((const void*)mma_gemm<4>, cudaFuncAttributeMaxDynamicSharedMemorySize, SMEM_BYTES);

    const dim3 blk(256);

    // 0) pre-split inputs (hi/lo) + weights (single)
    split_kernel<<<MROWS, 256>>>(x_rgb,  xrh, xrl, DMn, (size_t)MROWS * 256);
    split_kernel<<<MROWS, 256>>>(x_flow, xfh, xfl, DMn, (size_t)MROWS * 256);
    for (int i = 0; i < 8; i++)
        split1_kernel<<<DMn, 256>>>(W[i], Wd + (size_t)i * DMn * 256, DMn, (size_t)DMn * 256);

    // 1) projections
    const dim3 gP(DMn / 128, MROWS / 128, 1);
    #define WD(i) (Wd + (size_t)(i) * DMn * 256)
    mma_gemm<1><<<gP, blk, SMEM_BYTES>>>(xrh, xrl, WD(0), bW[0], nullptr,
                                         Qrh, Qrl, nullptr, nullptr, DMn, DMn, 1.f, 0, 0, 0, 0);
    mma_gemm<4><<<gP, blk, SMEM_BYTES>>>(xrh, xrl, WD(1), bW[1], nullptr,
                                         Kr, nullptr, nullptr, nullptr, DMn, DMn, 1.f, 0, 0, 0, 0);
    mma_gemm<2><<<gP, blk, SMEM_BYTES>>>(xrh, xrl, WD(2), bW[2], nullptr,
                                         V, nullptr, nullptr, nullptr, DMn, DMn, 1.f, 0, 0, 0, 0);
    mma_gemm<1><<<gP, blk, SMEM_BYTES>>>(xfh, xfl, WD(3), bW[3], nullptr,
                                         Qfh, Qfl, nullptr, nullptr, DMn, DMn, 1.f, 0, 0, 0, 0);
    mma_gemm<4><<<gP, blk, SMEM_BYTES>>>(xfh, xfl, WD(4), bW[4], nullptr,
                                         Kf, nullptr, nullptr, nullptr, DMn, DMn, 1.f, 0, 0, 0, 0);
    mma_gemm<2><<<gP, blk, SMEM_BYTES>>>(xfh, xfl, WD(5), bW[5], nullptr,
                                         V, nullptr, nullptr, nullptr, DMn, DMn, 1.f, 1, 0, 0, 0);

    // 2) scores (batched over b*h)
    const dim3 gS(Sn / 128, Sn / 128, Bn * Hn);
    mma_gemm<0><<<gS, blk, SMEM_BYTES>>>(Qrh, Qrl, Kr, nullptr, Sr,
                                         nullptr, nullptr, nullptr, nullptr,
                                         Sn, DKn, 0.125f, 0,
                                         Sn * 32, Sn * 32, (long long)Sn * Sn);
    mma_gemm<0><<<gS, blk, SMEM_BYTES>>>(Qfh, Qfl, Kf, nullptr, Sf,
                                         nullptr, nullptr, nullptr, nullptr,
                                         Sn, DKn, 0.125f, 0,
                                         Sn * 32, Sn * 32, (long long)Sn * Sn);

    // 3) softmax + max merge -> split fp16 P
    softmax_max_kernel<<<Bn * Hn * Sn, 256>>>(Sr, Sf, Ph, Pl);

    // 4) PV for both streams (combined V panel, N=128)
    mma_gemm<3><<<dim3(1, Sn / 128, Bn * Hn), blk, SMEM_BYTES>>>(
        Ph, Pl, V, nullptr, nullptr, Crh, Crl, Cfh, Cfl,
        128, Sn, 1.f, 0,
        (long long)Sn * 512, (long long)128 * 512, 0);

    // 5) output projections
    const dim3 gO(DMn / 128, MROWS / 128, 1);
    mma_gemm<0><<<gO, blk, SMEM_BYTES>>>(Crh, Crl, WD(6), bW[6], out,
                                         nullptr, nullptr, nullptr, nullptr,
                                         DMn, DMn, 1.f, 0, 0, 0, 0);
    mma_gemm<0><<<gO, blk, SMEM_BYTES>>>(Cfh, Cfl, WD(7), bW[7],
                                         out + (size_t)MROWS * DMn,
                                         nullptr, nullptr, nullptr, nullptr,
                                         DMn, DMn, 1.f, 0, 0, 0, 0);
}

// round 9
// speedup vs baseline: 4.4132x; 1.3984x over previous
#include <cuda_runtime.h>
#include <cuda_fp16.h>
#include <stdint.h>
#include <math.h>

#define Bn 8
#define Hn 8
#define Sn 1024
#define DMn 512
#define DKn 64
#define MROWS (Bn * 1024)   // 8192

// ---------------- scratch (device globals; no runtime allocation) ----------------
// all fp16 operands stored as uint32 (2 halves) in per-32k-chunk interleaved order
__device__ uint32_t g_xr[MROWS * 256], g_xf[MROWS * 256];      // inputs, single fp16
__device__ uint32_t g_W[8][DMn * 256];                         // weights, single fp16
__device__ uint32_t g_Qr[Bn*Hn*Sn*32], g_Qf[Bn*Hn*Sn*32];      // single fp16
__device__ uint32_t g_Kr[Bn*Hn*Sn*32], g_Kf[Bn*Hn*Sn*32];      // single fp16
__device__ uint32_t g_V[Bn*Hn*128*512];                        // single fp16 [bh][Vr d0-63|Vf d64-127][s-pairs]
__device__ uint32_t g_Shr[(size_t)Bn*Hn*Sn*512];               // scores fp16, plain layout
__device__ uint32_t g_Shf[(size_t)Bn*Hn*Sn*512];
__device__ uint32_t g_Ph[(size_t)Bn*Hn*Sn*512];                // merged P, single fp16, permuted
__device__ uint32_t g_Crh[MROWS * 256], g_Crl[MROWS * 256];    // contexts split (output-critical)
__device__ uint32_t g_Cfh[MROWS * 256], g_Cfl[MROWS * 256];

#define SMEM1 33792     // 1-pass kernels: 2x16KB stages (+sC overlap)
#define SMEM2 49152     // 2-pass kernels: 2x24KB stages

__device__ __forceinline__ uint32_t smem_u32(const void* p) {
    uint32_t a;
    asm("{ .reg .u64 t; cvta.to.shared.u64 t, %1; cvt.u32.u64 %0, t; }" : "=r"(a) : "l"(p));
    return a;
}

#define CP_ASYNC16(dst, src) \
    asm volatile("cp.async.cg.shared.global [%0], [%1], 16;" :: "r"(dst), "l"(src))
#define CP_COMMIT() asm volatile("cp.async.commit_group;" ::: "memory")
#define CP_WAIT(n)  asm volatile("cp.async.wait_group %0;" :: "n"(n) : "memory")

__device__ __forceinline__ uint32_t hpair(float a, float b) {
    __half2 t = __floats2half2_rn(a, b);
    return *reinterpret_cast<uint32_t*>(&t);
}

// permuted offset within a row for even k, matching SMEM physical tile order
__device__ __forceinline__ size_t perm_off(size_t rowbase32, int k) {
    const int c = k >> 5, t = (k & 31) >> 1;
    const int g = ((t >> 3) << 1) | ((t >> 1) & 1);
    const int s = ((t & 1) << 1) | ((t >> 2) & 1);
    return rowbase32 + c * 16 + g * 4 + s;
}

__device__ __forceinline__ void single_pair_store(
    uint32_t* __restrict__ dst, size_t rowbase32, int k, float v0, float v1)
{
    dst[perm_off(rowbase32, k)] = hpair(v0, v1);
}

__device__ __forceinline__ void split_pair_store(
    uint32_t* __restrict__ hi, uint32_t* __restrict__ lo,
    size_t rowbase32, int k, float v0, float v1)
{
    const size_t off = perm_off(rowbase32, k);
    __half h0 = __float2half_rn(v0), h1 = __float2half_rn(v1);
    hi[off] = hpair(__half2float(h0), __half2float(h1));
    lo[off] = hpair(v0 - __half2float(h0), v1 - __half2float(h1));
}

// ---------------- converters ----------------
__global__ void conv_x(const float* __restrict__ xr, const float* __restrict__ xf,
                       uint32_t* __restrict__ dr, uint32_t* __restrict__ df)
{
    const float* X = blockIdx.z ? xf : xr;
    uint32_t* D = blockIdx.z ? df : dr;
    const size_t i = (size_t)blockIdx.x * 256 + threadIdx.x;   // pair index
    const size_t row = i >> 8;
    const int k = (int)(i & 255) * 2;
    float2 v = *reinterpret_cast<const float2*>(X + row * 512 + k);
    single_pair_store(D, row * 256, k, v.x, v.y);
}

struct Ptrs8 { const float* p[8]; };
__global__ void conv_w(Ptrs8 wp, uint32_t* __restrict__ Wd)
{
    const int z = blockIdx.z;
    const float* X = wp.p[z];
    uint32_t* D = Wd + (size_t)z * DMn * 256;
    const size_t i = (size_t)blockIdx.x * 256 + threadIdx.x;
    const size_t row = i >> 8;
    const int k = (int)(i & 255) * 2;
    float2 v = *reinterpret_cast<const float2*>(X + row * 512 + k);
    single_pair_store(D, row * 256, k, v.x, v.y);
}

#define MMA(c, a, b) \
    asm volatile( \
        "mma.sync.aligned.m16n8k16.row.col.f32.f16.f16.f32 " \
        "{%0,%1,%2,%3},{%4,%5,%6,%7},{%8,%9},{%0,%1,%2,%3};" \
        : "+f"((c)[0]), "+f"((c)[1]), "+f"((c)[2]), "+f"((c)[3]) \
        : "r"((a)[0]), "r"((a)[1]), "r"((a)[2]), "r"((a)[3]), \
          "r"((b)[0]), "r"((b)[1]))

// ---------------- shared GEMM mainloop (double-buffered cp.async) ----------------
template <int NPASS>
__device__ __forceinline__ void gemm_core(
    char* smem, uint32_t sb, int tid,
    const uint32_t* __restrict__ Ahi, const uint32_t* __restrict__ Alo,
    const uint32_t* __restrict__ Bs,
    size_t aRow0, size_t bRow0, int rowA32, int nc,
    float acc[4][4][4])
{
    constexpr int T_ALOo = 8192;
    constexpr int T_Bo   = (NPASS == 2) ? 16384 : 8192;
    constexpr int STAGEo = (NPASS == 2) ? 24576 : 16384;

    const int w = tid >> 5, lane = tid & 31;
    const int wm = w >> 2, wn = w & 3;
    const int g = lane >> 2, tig = lane & 3;
    const int prr = tid >> 2, pg = tid & 3;

    #pragma unroll
    for (int i = 0; i < 4; i++)
        #pragma unroll
        for (int j = 0; j < 4; j++)
            #pragma unroll
            for (int c = 0; c < 4; c++) acc[i][j][c] = 0.f;

    auto issue = [&](int cc, int st) {
        const uint32_t so = sb + st * STAGEo;
        #pragma unroll
        for (int it = 0; it < 2; it++) {
            const int r = prr + it * 64;
            const uint32_t sw = (uint32_t)(r * 64 + ((pg * 16) ^ ((r & 2) << 4)));
            const size_t srcA = aRow0 + (size_t)r * rowA32 + cc * 16 + pg * 4;
            const size_t srcB = bRow0 + (size_t)r * rowA32 + cc * 16 + pg * 4;
            CP_ASYNC16(so + sw, Ahi + srcA);
            if (NPASS == 2) CP_ASYNC16(so + T_ALOo + sw, Alo + srcA);
            CP_ASYNC16(so + T_Bo + sw, Bs + srcB);
        }
    };

    issue(0, 0);
    CP_COMMIT();

    for (int cc = 0; cc < nc; cc++) {
        if (cc + 1 < nc) { issue(cc + 1, (cc + 1) & 1); CP_COMMIT(); CP_WAIT(1); }
        else             { CP_WAIT(0); }
        __syncthreads();
        const char* sm = smem + (cc & 1) * STAGEo;

        #pragma unroll
        for (int s = 0; s < 2; s++) {
            uint32_t bfr[4][2], Af[4][4];
            #pragma unroll
            for (int j = 0; j < 4; j++) {
                const int rB = wn * 32 + j * 8 + g;
                const uint32_t co = (uint32_t)((s * 32 + tig * 8) ^ ((rB & 2) << 4)) + rB * 64;
                uint2 u = *reinterpret_cast<const uint2*>(sm + T_Bo + co);
                bfr[j][0] = u.x; bfr[j][1] = u.y;
            }
            #pragma unroll
            for (int i = 0; i < 4; i++) {
                const int r0 = wm * 64 + i * 16 + g;
                const uint32_t co = (uint32_t)((s * 32 + tig * 8) ^ ((r0 & 2) << 4));
                uint2 u = *reinterpret_cast<const uint2*>(sm + r0 * 64 + co);
                uint2 v = *reinterpret_cast<const uint2*>(sm + (r0 + 8) * 64 + co);
                Af[i][0] = u.x; Af[i][1] = v.x; Af[i][2] = u.y; Af[i][3] = v.y;
            }
            #pragma unroll
            for (int i = 0; i < 4; i++)
                #pragma unroll
                for (int j = 0; j < 4; j++) MMA(acc[i][j], Af[i], bfr[j]);
            if (NPASS == 2) {
                #pragma unroll
                for (int i = 0; i < 4; i++) {
                    const int r0 = wm * 64 + i * 16 + g;
                    const uint32_t co = (uint32_t)((s * 32 + tig * 8) ^ ((r0 & 2) << 4));
                    uint2 u = *reinterpret_cast<const uint2*>(sm + T_ALOo + r0 * 64 + co);
                    uint2 v = *reinterpret_cast<const uint2*>(sm + T_ALOo + (r0 + 8) * 64 + co);
                    Af[i][0] = u.x; Af[i][1] = v.x; Af[i][2] = u.y; Af[i][3] = v.y;
                }
                #pragma unroll
                for (int i = 0; i < 4; i++)
                    #pragma unroll
                    for (int j = 0; j < 4; j++) MMA(acc[i][j], Af[i], bfr[j]);
            }
        }
        __syncthreads();
    }
}

// write this warp-group's half of acc into the sC staging tile
__device__ __forceinline__ void acc_to_sC(float* sC, float acc[4][4][4], int tid,
                                          int hh, float alpha, const float* bias, int bn)
{
    const int w = tid >> 5, lane = tid & 31;
    const int wm = w >> 2, wn = w & 3;
    const int g = lane >> 2, tig = lane & 3;
    if (wm == hh) {
        #pragma unroll
        for (int i = 0; i < 4; i++) {
            const int rl = i * 16 + g;
            #pragma unroll
            for (int j = 0; j < 4; j++) {
                const int cl = wn * 32 + j * 8 + 2 * tig;
                float bv0 = 0.f, bv1 = 0.f;
                if (bias) { bv0 = __ldg(bias + bn + cl); bv1 = __ldg(bias + bn + cl + 1); }
                float2 v0 = make_float2(acc[i][j][0] * alpha + bv0,
                                        acc[i][j][1] * alpha + bv1);
                float2 v1 = make_float2(acc[i][j][2] * alpha + bv0,
                                        acc[i][j][3] * alpha + bv1);
                *reinterpret_cast<float2*>(&sC[rl * 132 + cl]) = v0;
                *reinterpret_cast<float2*>(&sC[(rl + 8) * 132 + cl]) = v1;
            }
        }
    }
}

// ---------------- fused 6-projection kernel (1-pass A) ----------------
struct ProjArgs {
    const uint32_t *xr, *xf, *Wd;
    const float* bias[6];
    uint32_t *Qr, *Kr, *Qf, *Kf, *V;
};

__global__ void __launch_bounds__(256, 2) proj_kernel(ProjArgs pa)
{
    extern __shared__ char smem[];
    const uint32_t sb = smem_u32(smem);
    const int tid = threadIdx.x;
    const int z = blockIdx.z;
    const int bm = blockIdx.y * 128, bn = blockIdx.x * 128;

    const uint32_t* A = (z < 3) ? pa.xr : pa.xf;
    const uint32_t* Bw = pa.Wd + (size_t)z * DMn * 256;

    float acc[4][4][4];
    gemm_core<1>(smem, sb, tid, A, nullptr, Bw,
                 (size_t)bm * 256, (size_t)bn * 256, 256, 16, acc);

    float* sC = reinterpret_cast<float*>(smem);
    const int mode = z % 3;
    uint32_t* dst = (mode == 0) ? (z < 3 ? pa.Qr : pa.Qf)
                  : (mode == 1) ? (z < 3 ? pa.Kr : pa.Kf) : pa.V;
    const int vhalf = (z >= 3) ? 1 : 0;

    #pragma unroll
    for (int hh = 0; hh < 2; hh++) {
        acc_to_sC(sC, acc, tid, hh, 1.f, pa.bias[z], bn);
        __syncthreads();
        const int mbase = bm + hh * 64;
        const int b = mbase >> 10, h0 = bn >> 6;
        if (mode < 2) {
            const int s0 = mbase & 1023;
            for (int e = tid; e < 64 * 64; e += 256) {
                const int rl = e >> 6, p = e & 63, col = p * 2;
                const int hd = col >> 6, d = col & 63;
                const size_t rowIdx = ((size_t)(b * Hn + h0 + hd)) * Sn + s0 + rl;
                single_pair_store(dst, rowIdx * 32, d,
                                  sC[rl * 132 + col], sC[rl * 132 + col + 1]);
            }
        } else {
            const int sLoc = mbase & 1023;
            for (int e = tid; e < 32 * 128; e += 256) {
                const int col = e & 127, sl = (e >> 7) * 2;
                const int hd = col >> 6, d = col & 63;
                const size_t vrow = ((size_t)(b * Hn + h0 + hd)) * 128 + vhalf * 64 + d;
                single_pair_store(dst, vrow * 512, sLoc + sl,
                                  sC[sl * 132 + col], sC[(sl + 1) * 132 + col]);
            }
        }
        __syncthreads();
    }
}

// ---------------- fused score kernel: both streams, fp16 S out ----------------
__global__ void __launch_bounds__(256, 2) score_kernel(
    const uint32_t* __restrict__ Qr, const uint32_t* __restrict__ Kr,
    const uint32_t* __restrict__ Qf, const uint32_t* __restrict__ Kf,
    uint32_t* __restrict__ Shr, uint32_t* __restrict__ Shf)
{
    extern __shared__ char smem[];
    const uint32_t sb = smem_u32(smem);
    const int tid = threadIdx.x;
    const int z = blockIdx.z;
    const int stream = z >> 6, bh = z & 63;
    const int bm = blockIdx.y * 128, bn = blockIdx.x * 128;

    const uint32_t* A = stream ? Qf : Qr;
    const uint32_t* Bk = stream ? Kf : Kr;
    uint32_t* Sh = (stream ? Shf : Shr) + (size_t)bh * Sn * 512;

    float acc[4][4][4];
    gemm_core<1>(smem, sb, tid, A, nullptr, Bk,
                 (size_t)bh * Sn * 32 + (size_t)bm * 32,
                 (size_t)bh * Sn * 32 + (size_t)bn * 32, 32, 2, acc);

    float* sC = reinterpret_cast<float*>(smem);
    #pragma unroll
    for (int hh = 0; hh < 2; hh++) {
        acc_to_sC(sC, acc, tid, hh, 0.125f, nullptr, bn);
        __syncthreads();
        const int mbase = bm + hh * 64;
        for (int e = tid; e < 64 * 64; e += 256) {
            const int rl = e >> 6, p = e & 63, col = p * 2;
            Sh[(size_t)(mbase + rl) * 512 + ((bn + col) >> 1)] =
                hpair(sC[rl * 132 + col], sC[rl * 132 + col + 1]);
        }
        __syncthreads();
    }
}

// ---------------- fast exp ----------------
__device__ __forceinline__ float fexp(float x) {
    float t  = x * 1.4426950408889634f;
    float fi = rintf(t);
    float f  = t - fi;
    float p  = 1.3333558146428443e-3f;
    p = fmaf(p, f, 9.6181291076284770e-3f);
    p = fmaf(p, f, 5.5504108664821580e-2f);
    p = fmaf(p, f, 2.4022650695910072e-1f);
    p = fmaf(p, f, 6.9314718055994531e-1f);
    p = fmaf(p, f, 1.0f);
    int e = (int)fi;
    return __int_as_float(__float_as_int(p) + (e << 23));
}

// ---------------- softmax both streams + max merge -> single fp16 P ----------------
__global__ void __launch_bounds__(256) softmax_max_kernel(
    const uint32_t* __restrict__ Shr, const uint32_t* __restrict__ Shf,
    uint32_t* __restrict__ Ph)
{
    __shared__ float sred[8];
    const size_t row = blockIdx.x;
    const int t = threadIdx.x;

    uint2 ur = *reinterpret_cast<const uint2*>(Shr + row * 512 + 2 * t);
    uint2 uf = *reinterpret_cast<const uint2*>(Shf + row * 512 + 2 * t);
    float2 r01 = __half22float2(*reinterpret_cast<__half2*>(&ur.x));
    float2 r23 = __half22float2(*reinterpret_cast<__half2*>(&ur.y));
    float2 f01 = __half22float2(*reinterpret_cast<__half2*>(&uf.x));
    float2 f23 = __half22float2(*reinterpret_cast<__half2*>(&uf.y));
    float4 xr = make_float4(r01.x, r01.y, r23.x, r23.y);
    float4 xf = make_float4(f01.x, f01.y, f23.x, f23.y);

    float m = fmaxf(fmaxf(xr.x, xr.y), fmaxf(xr.z, xr.w));
    #pragma unroll
    for (int o = 16; o; o >>= 1) m = fmaxf(m, __shfl_xor_sync(0xffffffffu, m, o));
    if ((t & 31) == 0) sred[t >> 5] = m;
    __syncthreads();
    m = sred[0];
    #pragma unroll
    for (int i = 1; i < 8; i++) m = fmaxf(m, sred[i]);

    float er0 = fexp(xr.x - m), er1 = fexp(xr.y - m);
    float er2 = fexp(xr.z - m), er3 = fexp(xr.w - m);
    float s = er0 + er1 + er2 + er3;
    #pragma unroll
    for (int o = 16; o; o >>= 1) s += __shfl_xor_sync(0xffffffffu, s, o);
    __syncthreads();
    if ((t & 31) == 0) sred[t >> 5] = s;
    __syncthreads();
    s = sred[0];
    #pragma unroll
    for (int i = 1; i < 8; i++) s += sred[i];
    const float invZr = 1.0f / s;

    float mf = fmaxf(fmaxf(xf.x, xf.y), fmaxf(xf.z, xf.w));
    #pragma unroll
    for (int o = 16; o; o >>= 1) mf = fmaxf(mf, __shfl_xor_sync(0xffffffffu, mf, o));
    __syncthreads();
    if ((t & 31) == 0) sred[t >> 5] = mf;
    __syncthreads();
    mf = sred[0];
    #pragma unroll
    for (int i = 1; i < 8; i++) mf = fmaxf(mf, sred[i]);

    float ef0 = fexp(xf.x - mf), ef1 = fexp(xf.y - mf);
    float ef2 = fexp(xf.z - mf), ef3 = fexp(xf.w - mf);
    float sf = ef0 + ef1 + ef2 + ef3;
    #pragma unroll
    for (int o = 16; o; o >>= 1) sf += __shfl_xor_sync(0xffffffffu, sf, o);
    __syncthreads();
    if ((t & 31) == 0) sred[t >> 5] = sf;
    __syncthreads();
    sf = sred[0];
    #pragma unroll
    for (int i = 1; i < 8; i++) sf += sred[i];
    const float invZf = 1.0f / sf;

    float4 p;
    p.x = fmaxf(er0 * invZr, ef0 * invZf);
    p.y = fmaxf(er1 * invZr, ef1 * invZf);
    p.z = fmaxf(er2 * invZr, ef2 * invZf);
    p.w = fmaxf(er3 * invZr, ef3 * invZf);

    single_pair_store(Ph, row * 512, 4 * t,     p.x, p.y);
    single_pair_store(Ph, row * 512, 4 * t + 2, p.z, p.w);
}

// ---------------- PV kernel: 1-pass, split C output ----------------
__global__ void __launch_bounds__(256, 2) pv_kernel(
    const uint32_t* __restrict__ Ph, const uint32_t* __restrict__ V,
    uint32_t* __restrict__ Crh, uint32_t* __restrict__ Crl,
    uint32_t* __restrict__ Cfh, uint32_t* __restrict__ Cfl)
{
    extern __shared__ char smem[];
    const uint32_t sb = smem_u32(smem);
    const int tid = threadIdx.x;
    const int z = blockIdx.z;
    const int bm = blockIdx.y * 128;

    float acc[4][4][4];
    gemm_core<1>(smem, sb, tid, Ph, nullptr, V,
                 (size_t)z * Sn * 512 + (size_t)bm * 512,
                 (size_t)z * 128 * 512, 512, 32, acc);

    float* sC = reinterpret_cast<float*>(smem);
    const int b = z >> 3, h = z & 7;
    #pragma unroll
    for (int hh = 0; hh < 2; hh++) {
        acc_to_sC(sC, acc, tid, hh, 1.f, nullptr, 0);
        __syncthreads();
        const int mbase = bm + hh * 64;
        for (int e = tid; e < 64 * 64; e += 256) {
            const int rl = e >> 6, p = e & 63;
            const int str = p >> 5, d = (p & 31) * 2;
            const int col = str * 64 + d;
            const size_t rowIdx = (size_t)b * Sn + mbase + rl;
            uint32_t* H = str ? Cfh : Crh;
            uint32_t* L = str ? Cfl : Crl;
            split_pair_store(H, L, rowIdx * 256, h * 64 + d,
                             sC[rl * 132 + col], sC[rl * 132 + col + 1]);
        }
        __syncthreads();
    }
}

// ---------------- fused output projections (2-pass A) ----------------
__global__ void __launch_bounds__(256, 2) outproj_kernel(
    const uint32_t* __restrict__ Crh, const uint32_t* __restrict__ Crl,
    const uint32_t* __restrict__ Cfh, const uint32_t* __restrict__ Cfl,
    const uint32_t* __restrict__ Wd, const float* __restrict__ b6,
    const float* __restrict__ b7, float* __restrict__ out)
{
    extern __shared__ char smem[];
    const uint32_t sb = smem_u32(smem);
    const int tid = threadIdx.x;
    const int z = blockIdx.z;
    const int bm = blockIdx.y * 128, bn = blockIdx.x * 128;

    const uint32_t* Ahi = z ? Cfh : Crh;
    const uint32_t* Alo = z ? Cfl : Crl;
    const uint32_t* Bw = Wd + (size_t)(6 + z) * DMn * 256;
    const float* bias = z ? b7 : b6;
    float* C = out + (size_t)z * MROWS * DMn;

    float acc[4][4][4];
    gemm_core<2>(smem, sb, tid, Ahi, Alo, Bw,
                 (size_t)bm * 256, (size_t)bn * 256, 256, 16, acc);

    float* sC = reinterpret_cast<float*>(smem);
    #pragma unroll
    for (int hh = 0; hh < 2; hh++) {
        acc_to_sC(sC, acc, tid, hh, 1.f, bias, bn);
        __syncthreads();
        const int mbase = bm + hh * 64;
        for (int e = tid * 4; e < 64 * 128; e += 1024) {
            const int row = e >> 7, col = e & 127;
            float4 v = make_float4(sC[row * 132 + col],     sC[row * 132 + col + 1],
                                   sC[row * 132 + col + 2], sC[row * 132 + col + 3]);
            *reinterpret_cast<float4*>(&C[(size_t)(mbase + row) * DMn + bn + col]) = v;
        }
        __syncthreads();
    }
}

// ---------------- host ----------------
extern "C" void kernel_launch(void* const* d_in, const int* in_sizes, int n_in,
                              void* d_out, int out_size)
{
    const float* x_rgb  = (const float*)d_in[0];
    const float* x_flow = (const float*)d_in[1];
    Ptrs8 wp; const float* bW[8];
    for (int i = 0; i < 8; i++) { wp.p[i] = (const float*)d_in[2 + 2*i]; bW[i] = (const float*)d_in[3 + 2*i]; }
    float* out = (float*)d_out;

    uint32_t *xr,*xf,*Wd,*Qr,*Qf,*Kr,*Kf,*V,*Shr,*Shf,*Ph,*Crh,*Crl,*Cfh,*Cfl;
    cudaGetSymbolAddress((void**)&xr, g_xr);   cudaGetSymbolAddress((void**)&xf, g_xf);
    cudaGetSymbolAddress((void**)&Wd, g_W);
    cudaGetSymbolAddress((void**)&Qr, g_Qr);   cudaGetSymbolAddress((void**)&Qf, g_Qf);
    cudaGetSymbolAddress((void**)&Kr, g_Kr);   cudaGetSymbolAddress((void**)&Kf, g_Kf);
    cudaGetSymbolAddress((void**)&V, g_V);
    cudaGetSymbolAddress((void**)&Shr, g_Shr); cudaGetSymbolAddress((void**)&Shf, g_Shf);
    cudaGetSymbolAddress((void**)&Ph, g_Ph);
    cudaGetSymbolAddress((void**)&Crh, g_Crh); cudaGetSymbolAddress((void**)&Crl, g_Crl);
    cudaGetSymbolAddress((void**)&Cfh, g_Cfh); cudaGetSymbolAddress((void**)&Cfl, g_Cfl);

    cudaFuncSetAttribute((const void*)proj_kernel,    cudaFuncAttributeMaxDynamicSharedMemorySize, SMEM1);
    cudaFuncSetAttribute((const void*)score_kernel,   cudaFuncAttributeMaxDynamicSharedMemorySize, SMEM1);
    cudaFuncSetAttribute((const void*)pv_kernel,      cudaFuncAttributeMaxDynamicSharedMemorySize, SMEM1);
    cudaFuncSetAttribute((const void*)outproj_kernel, cudaFuncAttributeMaxDynamicSharedMemorySize, SMEM2);

    // 0) conversions: 2 launches
    conv_x<<<dim3(MROWS, 1, 2), 256>>>(x_rgb, x_flow, xr, xf);
    conv_w<<<dim3(DMn, 1, 8), 256>>>(wp, Wd);

    // 1) all six projections in one launch
    ProjArgs pa;
    pa.xr = xr; pa.xf = xf; pa.Wd = Wd;
    for (int i = 0; i < 6; i++) pa.bias[i] = bW[i];
    pa.Qr = Qr; pa.Kr = Kr; pa.Qf = Qf; pa.Kf = Kf; pa.V = V;
    proj_kernel<<<dim3(DMn / 128, MROWS / 128, 6), 256, SMEM1>>>(pa);

    // 2) both score batches in one launch (fp16 S out)
    score_kernel<<<dim3(Sn / 128, Sn / 128, 128), 256, SMEM1>>>(Qr, Kr, Qf, Kf, Shr, Shf);

    // 3) softmax + max merge -> single fp16 P
    softmax_max_kernel<<<Bn * Hn * Sn, 256>>>(Shr, Shf, Ph);

    // 4) PV for both streams (1-pass)
    pv_kernel<<<dim3(1, Sn / 128, Bn * Hn), 256, SMEM1>>>(Ph, V, Crh, Crl, Cfh, Cfl);

    // 5) both output projections in one launch (2-pass)
    outproj_kernel<<<dim3(DMn / 128, MROWS / 128, 2), 256, SMEM2>>>(
        Crh, Crl, Cfh, Cfl, Wd, bW[6], bW[7], out);
}